// round 14
// baseline (speedup 1.0000x reference)
#include <cuda_runtime.h>
#include <math.h>
#include <stdint.h>

#define B_   1024
#define T_   50
#define IN_  784
#define NSLOT 128
#define D_   40
#define H_   200
#define R_   4
#define C_   5
#define G4H  800
#define KRH  360
#define BT   (B_*T_)
#define GB   8            // batches per block
#define NBLK (B_/GB)      // 128
#define TPB  512
#define NW   (TPB/32)     // 16 warps
#define MSTR 41           // padded M row stride (conflict-free)

// ---------------- device globals ----------------
__device__ float g_Xpre[BT * G4H];                   // images@Wx + b + offset row (fp32)
__device__ __align__(16) uint32_t g_W4P[50*45*96];   // 24-bit packed tf32 Wrh (lossless)
__device__ __align__(16) float g_WpM[21*25*64];      // mma-fragment tf32 Wp (float2/lane)
__device__ float g_WcT[C_ * KRH];                    // tf32-rounded Wc, TRANSPOSED [C][KRH]
__device__ __align__(16) float g_Wxr[IN_ * G4H];     // tf32-rounded Wx rows [0,784)
__device__ float g_rowloss[BT];
__device__ float g_rowcorr[BT];

__device__ __forceinline__ float tf32r(float x) {
    float y;
    asm("cvt.rna.tf32.f32 %0, %1;" : "=f"(y) : "f"(x));
    return y;
}

// ---------------- precise transcendentals (fast-math immune) ----------------
__device__ __forceinline__ float exp_acc(float x) {
    x = fminf(fmaxf(x, -87.0f), 88.0f);
    float n = rintf(x * 1.44269504088896341f);
    float r = fmaf(n, -0.693359375f, x);
    r = fmaf(n, 2.12194440e-4f, r);
    float z = r * r;
    float p = 1.9875691500e-4f;
    p = fmaf(p, r, 1.3981999507e-3f);
    p = fmaf(p, r, 8.3334519073e-3f);
    p = fmaf(p, r, 4.1665795894e-2f);
    p = fmaf(p, r, 1.6666665459e-1f);
    p = fmaf(p, r, 5.0000001201e-1f);
    float res = fmaf(p, z, r) + 1.0f;
    int i = (int)n;
    float scale = __int_as_float((i + 127) << 23);
    return res * scale;
}
__device__ __forceinline__ float expm1_small(float y) {
    float p = 2.7557319e-7f;
    p = fmaf(p, y, 2.4801587e-5f);
    p = fmaf(p, y, 1.9841270e-4f);
    p = fmaf(p, y, 1.3888889e-3f);
    p = fmaf(p, y, 8.3333333e-3f);
    p = fmaf(p, y, 4.1666667e-2f);
    p = fmaf(p, y, 1.6666667e-1f);
    p = fmaf(p, y, 0.5f);
    p = fmaf(p, y, 1.0f);
    return y * p;
}
__device__ __forceinline__ float tanh_acc(float x) {
    float a = fabsf(x);
    float t;
    if (a < 0.51f) {
        float em1 = expm1_small(2.0f * a);
        t = __fdiv_rn(em1, em1 + 2.0f);
    } else if (a < 9.1f) {
        float e = exp_acc(2.0f * a);
        t = 1.0f - __fdiv_rn(2.0f, e + 1.0f);
    } else {
        t = 1.0f;
    }
    return copysignf(t, x);
}
__device__ __forceinline__ float sigm(float x) {
    float e = exp_acc(-x);
    return __fdiv_rn(1.0f, 1.0f + e);
}

// ---------------- init: build packed / pre-rounded weights ----------------
__global__ void init_kernel(const float* __restrict__ Wx, const float* __restrict__ Wh,
                            const float* __restrict__ Wp, const float* __restrict__ Wc) {
    int idx = blockIdx.x * blockDim.x + threadIdx.x;
    int stride = gridDim.x * blockDim.x;
    for (int i = idx; i < 50*45*32; i += stride) {
        int lane = i & 31;
        int k8 = (i >> 5) % 45;
        int p = (i >> 5) / 45;
        int lr = lane >> 2, lc = lane & 3;
        uint32_t vb[4];
#pragma unroll
        for (int q = 0; q < 4; q++) {
            int row = k8 * 8 + (q & 1) * 4 + lc;
            int col = p * 16 + (q >> 1) * 8 + lr;
            float v = (row < R_*D_) ? Wx[(size_t)(IN_ + C_ + row) * G4H + col]
                                    : Wh[(size_t)(row - R_*D_) * G4H + col];
            vb[q] = __float_as_uint(tf32r(v));
        }
        uint32_t a = vb[0], b = vb[1], c = vb[2], d = vb[3];
        uint32_t u0 = (a >> 8) | (b << 16);
        uint32_t u1 = (b >> 16) | ((c >> 8) << 16);
        uint32_t u2 = (c >> 24) | (d & 0xFFFFFF00u);
        int base = (p * 45 + k8) * 96 + lane;
        g_W4P[base]      = u0;
        g_W4P[base + 32] = u1;
        g_W4P[base + 64] = u2;
    }
    for (int i = idx; i < 21*25*32; i += stride) {
        int lane = i & 31;
        int k8 = (i >> 5) % 25;
        int q = (i >> 5) / 25;
        int lr = lane >> 2, lc = lane & 3;
        int col = q * 8 + lr;
        int row0 = k8 * 8 + lc, row1 = row0 + 4;
        float b0 = (col < 164) ? tf32r(Wp[row0 * 164 + col]) : 0.f;
        float b1 = (col < 164) ? tf32r(Wp[row1 * 164 + col]) : 0.f;
        int base = ((q * 25 + k8) * 32 + lane) * 2;
        g_WpM[base]     = b0;
        g_WpM[base + 1] = b1;
    }
    for (int i = idx; i < KRH * C_; i += stride) {
        int j = i / C_, cl = i - (i / C_) * C_;
        g_WcT[cl * KRH + j] = tf32r(Wc[i]);
    }
    for (int i = idx; i < IN_ * G4H; i += stride) g_Wxr[i] = tf32r(Wx[i]);
}

// ---------------- tf32 mma helper ----------------
__device__ __forceinline__ void mma_tf32(float& c0, float& c1, float& c2, float& c3,
                                         uint32_t a0, uint32_t a1, uint32_t a2, uint32_t a3,
                                         uint32_t b0, uint32_t b1) {
    asm volatile(
        "mma.sync.aligned.m16n8k8.row.col.f32.tf32.tf32.f32 "
        "{%0,%1,%2,%3}, {%4,%5,%6,%7}, {%8,%9}, {%0,%1,%2,%3};\n"
        : "+f"(c0), "+f"(c1), "+f"(c2), "+f"(c3)
        : "r"(a0), "r"(a1), "r"(a2), "r"(a3), "r"(b0), "r"(b1));
}

// ---------------- gemm0: Xpre = images @ Wx[:784] + b + offset row  (BM=128,BN=160) -------
#define NKT 25
#define G0_SMEM_FLOATS (2*128*36 + 2*32*164)    // 9216 + 10496 = 19712
__global__ __launch_bounds__(256) void gemm0_kernel(
    const float* __restrict__ A, const float* __restrict__ WxFull,
    const float* __restrict__ b_lstm, const int* __restrict__ labs,
    float* __restrict__ Cout)
{
    extern __shared__ float SG[];
    float* As = SG;            // [2][128][36]
    float* Bs = SG + 9216;     // [2][32][164]
    int tid = threadIdx.x, lane = tid & 31, warp = tid >> 5;
    int wm = warp >> 2, wn = warp & 3;    // 2M x 4N warps; warp tile 64x40
    int m0 = blockIdx.y * 128, n0 = blockIdx.x * 160;
    int lr = lane >> 2, lc = lane & 3;
    float c[4][5][4];
#pragma unroll
    for (int i = 0; i < 4; i++)
#pragma unroll
        for (int j = 0; j < 5; j++)
#pragma unroll
            for (int q = 0; q < 4; q++) c[i][j][q] = 0.f;

#define G0_ISSUE(IT) do {                                                       \
    int st_ = (IT) & 1;                                                         \
    int k0_ = (IT) * 32;                                                        \
    _Pragma("unroll")                                                           \
    for (int i_ = 0; i_ < 4; i_++) {                                            \
        int e_ = tid + i_ * 256;                                                \
        int row_ = e_ >> 3, c4_ = (e_ & 7) * 4;                                 \
        uint32_t sz_ = (k0_ + c4_ + 3 < IN_) ? 16u : 0u;                        \
        const float* src_ = A + (size_t)(m0 + row_) * IN_ + (sz_ ? (k0_ + c4_) : 0); \
        uint32_t da_ = (uint32_t)__cvta_generic_to_shared(&As[st_*4608 + row_*36 + c4_]); \
        asm volatile("cp.async.ca.shared.global [%0], [%1], 16, %2;" :: "r"(da_), "l"(src_), "r"(sz_)); \
    }                                                                           \
    _Pragma("unroll")                                                           \
    for (int i_ = 0; i_ < 5; i_++) {                                            \
        int e_ = tid + i_ * 256;                                                \
        int row_ = e_ / 40, c4_ = (e_ % 40) * 4;                                \
        int krow_ = k0_ + row_;                                                 \
        uint32_t sz_ = (krow_ < IN_) ? 16u : 0u;                                \
        const float* src_ = g_Wxr + (sz_ ? ((size_t)krow_ * G4H + n0 + c4_) : 0); \
        uint32_t da_ = (uint32_t)__cvta_generic_to_shared(&Bs[st_*5248 + row_*164 + c4_]); \
        asm volatile("cp.async.ca.shared.global [%0], [%1], 16, %2;" :: "r"(da_), "l"(src_), "r"(sz_)); \
    }                                                                           \
    asm volatile("cp.async.commit_group;");                                     \
} while (0)

    G0_ISSUE(0);
    for (int it = 0; it < NKT; it++) {
        if (it + 1 < NKT) {
            G0_ISSUE(it + 1);
            asm volatile("cp.async.wait_group 1;");
        } else {
            asm volatile("cp.async.wait_group 0;");
        }
        __syncthreads();
        int st = it & 1;
        const float* Ast = As + st * 4608;
        const float* Bst = Bs + st * 5248;
#pragma unroll
        for (int k8 = 0; k8 < 4; k8++) {
            int kk = k8 * 8;
            uint32_t a[4][4];
#pragma unroll
            for (int mt = 0; mt < 4; mt++) {
                int arow = wm * 64 + mt * 16 + lr;
                a[mt][0] = __float_as_uint(tf32r(Ast[arow*36 + kk + lc]));
                a[mt][1] = __float_as_uint(tf32r(Ast[(arow + 8)*36 + kk + lc]));
                a[mt][2] = __float_as_uint(tf32r(Ast[arow*36 + kk + lc + 4]));
                a[mt][3] = __float_as_uint(tf32r(Ast[(arow + 8)*36 + kk + lc + 4]));
            }
#pragma unroll
            for (int nt = 0; nt < 5; nt++) {
                int bcol = wn * 40 + nt * 8 + lr;
                uint32_t b0 = __float_as_uint(Bst[(kk + lc)*164 + bcol]);
                uint32_t b1 = __float_as_uint(Bst[(kk + lc + 4)*164 + bcol]);
#pragma unroll
                for (int mt = 0; mt < 4; mt++)
                    mma_tf32(c[mt][nt][0], c[mt][nt][1], c[mt][nt][2], c[mt][nt][3],
                             a[mt][0], a[mt][1], a[mt][2], a[mt][3], b0, b1);
            }
        }
        __syncthreads();
    }

#pragma unroll
    for (int mt = 0; mt < 4; mt++) {
        int row0 = m0 + wm * 64 + mt * 16 + lr;
#pragma unroll
        for (int rr = 0; rr < 2; rr++) {
            int row = row0 + rr * 8;
            int tt = row % T_;
            int lab = (tt > 0) ? labs[row - 1] : 0;
#pragma unroll
            for (int nt = 0; nt < 5; nt++) {
                int col = n0 + wn * 40 + nt * 8 + 2 * lc;
#pragma unroll
                for (int cc = 0; cc < 2; cc++) {
                    int cg = col + cc;     // always < 800 (160*5 = 800 exact)
                    float v = c[mt][nt][rr * 2 + cc];
                    v += b_lstm[cg];
                    if (tt > 0) v += tf32r(WxFull[(size_t)(IN_ + lab) * G4H + cg]);
                    Cout[(size_t)row * G4H + cg] = v;
                }
            }
        }
    }
}

// ---------------- fused persistent recurrence kernel (R13 structure; L parallelized) ------
#define OFF_SM   0                      // GB*5248 = 41984
#define OFF_RHT  41984                  // GB*361 = 2888 -> 44872
#define OFF_GU   44872                  // 6400 gates; union: SWR+MN+SKN
#define OFF_SWR  (OFF_GU)               // 4096
#define OFF_MN   (OFF_GU + 4096)        // 1024
#define OFF_SKN  (OFF_GU + 5120)        // 1280
#define OFF_WRO  51272                  // 4096 -> 55368
#define OFF_WU   55368                  // 1024 -> 56392
#define OFF_SKT  56392                  // 1280 -> 57672
#define OFF_KN   57672                  // 32
#define OFF_SSIG 57704                  // 32
#define OFF_SLOG 57736                  // 40
#define OFF_LU   57776                  // 32 ints
#define SMEM_FLOATS 57808
#define SMEM_BYTES  (SMEM_FLOATS * 4)   // 231232 <= 232448

__global__ __launch_bounds__(TPB, 1) void fused_kernel(
    const float* __restrict__ bp, const float* __restrict__ bc,
    const int* __restrict__ labels, float* __restrict__ out)
{
    extern __shared__ float S[];
    int tid = threadIdx.x;
    int lane = tid & 31, warp = tid >> 5;
    int bb = blockIdx.x * GB;
    int* s_luI = (int*)(S + OFF_LU);
    const int lr = lane >> 2, lc = lane & 3;

    float c_reg[4] = {0.f, 0.f, 0.f, 0.f};

    // ---- state init ----
    for (int i = tid; i < GB * NSLOT * MSTR; i += TPB) S[OFF_SM + i] = 1e-6f;
    for (int i = tid; i < GB * 361; i += TPB) {
        int j = i % 361;
        S[OFF_RHT + i] = (j < R_*D_) ? tf32r(1e-6f) : 0.f;
    }
    for (int i = tid; i < GB * NSLOT; i += TPB) S[OFF_WU + i] = ((i & 127) == 0) ? 1.f : 0.f;
    for (int i = tid; i < GB * 512; i += TPB)   S[OFF_WRO + i] = ((i & 127) == 0) ? 1.f : 0.f;
    __syncthreads();

    for (int t = 0; t < T_; t++) {
        // ---- A: gates GEMM [8x360]@[360x800] via mma + 24-bit packed W, + Xpre epilogue ----
        {
            const float* rhRow = S + OFF_RHT + lr * 361;
            for (int p = warp; p < 50; p += NW) {
                float c00 = 0.f, c01 = 0.f, c02 = 0.f, c03 = 0.f;
                float c10 = 0.f, c11 = 0.f, c12 = 0.f, c13 = 0.f;
                const uint32_t* wp = g_W4P + p * (45 * 96) + lane;
#pragma unroll 5
                for (int k8 = 0; k8 < 45; k8++) {
                    uint32_t u0 = wp[0], u1 = wp[32], u2 = wp[64];
                    wp += 96;
                    uint32_t wx = u0 << 8;
                    uint32_t wy = ((u0 >> 24) << 8) | (u1 << 16);
                    uint32_t wz = ((u1 >> 16) << 8) | (u2 << 24);
                    uint32_t ww = u2 & 0xFFFFFF00u;
                    uint32_t a0 = __float_as_uint(rhRow[k8 * 8 + lc]);
                    uint32_t a2 = __float_as_uint(rhRow[k8 * 8 + 4 + lc]);
                    mma_tf32(c00, c01, c02, c03, a0, 0u, a2, 0u, wx, wy);
                    mma_tf32(c10, c11, c12, c13, a0, 0u, a2, 0u, wz, ww);
                }
                int col0 = p * 16 + 2 * lc;
                const float* xp = g_Xpre + ((size_t)(bb + lr) * T_ + t) * G4H;
                float* gr = S + OFF_GU + lr * 800;
                gr[col0]     = c00 + xp[col0];
                gr[col0 + 1] = c01 + xp[col0 + 1];
                gr[col0 + 8] = c10 + xp[col0 + 8];
                gr[col0 + 9] = c11 + xp[col0 + 9];
            }
        }
        __syncthreads();

        // ---- B: LSTM pointwise ----
#pragma unroll
        for (int s = 0; s < 4; s++) {
            int i = tid + s * TPB;
            if (i < GB * H_) {
                int g = i / H_, u = i - g * H_;
                const float* gg = S + OFF_GU + g * 800;
                float ig = gg[u], fg = gg[200 + u], gz = gg[400 + u], og = gg[600 + u];
                float c_new = sigm(fg) * c_reg[s] + sigm(ig) * tanh_acc(gz);
                c_reg[s] = c_new;
                float h = sigm(og) * tanh_acc(c_new);
                S[OFF_RHT + g * 361 + R_*D_ + u] = tf32r(h);
            }
        }
        __syncthreads();

        // ---- C: keys via mma [8x200]@[200x164] + M row norms ----
        {
            const float* hRow = S + OFF_RHT + lr * 361 + R_*D_;
            for (int q = warp; q < 21; q += NW) {
                float k0v = 0.f, k1v = 0.f, k2d = 0.f, k3d = 0.f;
                const float2* wp2 = reinterpret_cast<const float2*>(g_WpM) + (q * 25) * 32 + lane;
#pragma unroll 5
                for (int k8 = 0; k8 < 25; k8++) {
                    float2 b = wp2[k8 * 32];
                    uint32_t a0 = __float_as_uint(hRow[k8 * 8 + lc]);
                    uint32_t a2 = __float_as_uint(hRow[k8 * 8 + 4 + lc]);
                    mma_tf32(k0v, k1v, k2d, k3d, a0, 0u, a2, 0u,
                             __float_as_uint(b.x), __float_as_uint(b.y));
                }
                int g = lr;
#pragma unroll
                for (int cc = 0; cc < 2; cc++) {
                    int j = q * 8 + 2 * lc + cc;
                    if (j < 164) {
                        float acc = (cc ? k1v : k0v) + bp[j];
                        int r = j / 41, w = j - r * 41;
                        if (w < D_) S[OFF_SKT + g * 160 + r * 40 + w] = tanh_acc(acc);
                        else        S[OFF_SSIG + g * 4 + r] = sigm(acc);
                    }
                }
            }
        }
#pragma unroll
        for (int s = 0; s < 2; s++) {
            int p = tid + s * TPB;
            int g = p >> 7, n = p & 127;
            const float* Mr = S + OFF_SM + g * NSLOT * MSTR + n * MSTR;
            float ss = 0.f;
            for (int d = 0; d < D_; d++) ss = fmaf(Mr[d], Mr[d], ss);
            S[OFF_MN + p] = __fsqrt_rn(ss) + 1e-8f;
        }
        __syncthreads();

        // ---- D: key norms (tid<32) + LU selection (warps 8..15) ----
        if (tid < 32) {
            int g = tid >> 2, r = tid & 3;
            const float* kk = S + OFF_SKT + g * 160 + r * 40;
            float ss = 0.f;
            for (int d = 0; d < D_; d++) ss = fmaf(kk[d], kk[d], ss);
            S[OFF_KN + tid] = __fsqrt_rn(ss) + 1e-8f;
        } else if (warp >= 8 && warp < 16) {
            int g = warp - 8;
            const float* wu = S + OFF_WU + g * NSLOT;
            float v0 = wu[lane], v1 = wu[lane + 32], v2 = wu[lane + 64], v3 = wu[lane + 96];
            int i0 = lane, i1 = lane + 32, i2 = lane + 64, i3 = lane + 96;
#pragma unroll
            for (int s = 0; s < R_; s++) {
                float bv = v0; int bi = i0;
                if (v1 < bv || (v1 == bv && i1 < bi)) { bv = v1; bi = i1; }
                if (v2 < bv || (v2 == bv && i2 < bi)) { bv = v2; bi = i2; }
                if (v3 < bv || (v3 == bv && i3 < bi)) { bv = v3; bi = i3; }
#pragma unroll
                for (int o = 16; o > 0; o >>= 1) {
                    float ov = __shfl_xor_sync(0xffffffffu, bv, o);
                    int   oi = __shfl_xor_sync(0xffffffffu, bi, o);
                    if (ov < bv || (ov == bv && oi < bi)) { bv = ov; bi = oi; }
                }
                if (lane == 0) s_luI[g * 4 + s] = bi;
                if      (bi == i0) v0 = 3.0e38f;
                else if (bi == i1) v1 = 3.0e38f;
                else if (bi == i2) v2 = 3.0e38f;
                else if (bi == i3) v3 = 3.0e38f;
            }
        }
        __syncthreads();

        // ---- E: round keys; build skn ----
#pragma unroll
        for (int s = 0; s < 3; s++) {
            int i = tid + s * TPB;
            if (i < GB * 160) {
                int g = i / 160, j = i - g * 160;
                int r = j / 40;
                float raw = S[OFF_SKT + i];
                float nrm = S[OFF_KN + g * 4 + r];
                S[OFF_SKN + i] = tf32r(__fdiv_rn(raw, nrm));
                S[OFF_SKT + i] = tf32r(raw);
            }
        }
        __syncthreads();

        // ---- F: cosine logits ----
#pragma unroll
        for (int s = 0; s < 2; s++) {
            int p = tid + s * TPB;
            int g = p >> 7, n = p & 127;
            const float* Mr = S + OFF_SM + g * NSLOT * MSTR + n * MSTR;
            const float* kn = S + OFF_SKN + g * 160;
            float rinv = __fdiv_rn(1.f, S[OFF_MN + p]);
            float a0 = 0.f, a1 = 0.f, a2 = 0.f, a3 = 0.f;
            for (int d = 0; d < D_; d++) {
                float mn = tf32r(Mr[d] * rinv);
                a0 = fmaf(mn, kn[d],       a0);
                a1 = fmaf(mn, kn[40 + d],  a1);
                a2 = fmaf(mn, kn[80 + d],  a2);
                a3 = fmaf(mn, kn[120 + d], a3);
            }
            float* sw = S + OFF_SWR + g * 512;
            sw[n] = a0; sw[128 + n] = a1; sw[256 + n] = a2; sw[384 + n] = a3;
        }
        __syncthreads();

        // ---- G: softmax per (g,r) ----
        for (int row = warp; row < GB * R_; row += NW) {
            int g = row >> 2, r = row & 3;
            float* sw = S + OFF_SWR + g * 512 + r * 128;
            float v0 = sw[lane], v1 = sw[lane + 32], v2 = sw[lane + 64], v3 = sw[lane + 96];
            float mx = fmaxf(fmaxf(v0, v1), fmaxf(v2, v3));
            for (int o = 16; o > 0; o >>= 1) mx = fmaxf(mx, __shfl_xor_sync(0xffffffffu, mx, o));
            float e0 = exp_acc(v0 - mx), e1 = exp_acc(v1 - mx), e2 = exp_acc(v2 - mx), e3 = exp_acc(v3 - mx);
            float ssum = e0 + e1 + e2 + e3;
            for (int o = 16; o > 0; o >>= 1) ssum += __shfl_xor_sync(0xffffffffu, ssum, o);
            sw[lane]      = __fdiv_rn(e0, ssum);
            sw[lane + 32] = __fdiv_rn(e1, ssum);
            sw[lane + 64] = __fdiv_rn(e2, ssum);
            sw[lane + 96] = __fdiv_rn(e3, ssum);
        }
        __syncthreads();

        // ---- H: usage update + wrOld<-swr + memory write + round swr in place ----
#pragma unroll
        for (int s = 0; s < 2; s++) {
            int p = tid + s * TPB;
            int g = p >> 7, n = p & 127;
            float* wro = S + OFF_WRO + g * 512;
            float* sw  = S + OFF_SWR + g * 512;
            int lu0 = s_luI[g*4], lu1 = s_luI[g*4+1], lu2 = s_luI[g*4+2], lu3 = s_luI[g*4+3];
            float wlu = (n == lu0 || n == lu1 || n == lu2 || n == lu3) ? 1.f : 0.f;
            float sg0 = S[OFF_SSIG + g*4], sg1 = S[OFF_SSIG + g*4+1];
            float sg2 = S[OFF_SSIG + g*4+2], sg3 = S[OFF_SSIG + g*4+3];
            float wo0 = wro[n], wo1 = wro[128+n], wo2 = wro[256+n], wo3 = wro[384+n];
            float ww0 = sg0 * wo0 + (1.f - sg0) * wlu;
            float ww1 = sg1 * wo1 + (1.f - sg1) * wlu;
            float ww2 = sg2 * wo2 + (1.f - sg2) * wlu;
            float ww3 = sg3 * wo3 + (1.f - sg3) * wlu;
            float sr0 = sw[n], sr1 = sw[128+n], sr2 = sw[256+n], sr3 = sw[384+n];
            float v = 0.95f * S[OFF_WU + p];
            v += sr0 + ww0; v += sr1 + ww1; v += sr2 + ww2; v += sr3 + ww3;
            S[OFF_WU + p] = v;
            wro[n] = sr0; wro[128+n] = sr1; wro[256+n] = sr2; wro[384+n] = sr3;
            sw[n] = tf32r(sr0); sw[128+n] = tf32r(sr1); sw[256+n] = tf32r(sr2); sw[384+n] = tf32r(sr3);
            float wt0 = tf32r(ww0), wt1 = tf32r(ww1), wt2 = tf32r(ww2), wt3 = tf32r(ww3);
            float* Mr = S + OFF_SM + g * NSLOT * MSTR + n * MSTR;
            const float* kT = S + OFF_SKT + g * 160;
            bool zero_base = (n == lu3);
            for (int d = 0; d < D_; d++) {
                float base = zero_base ? 0.f : Mr[d];
                float add = 0.f;
                add = fmaf(wt0, kT[d],       add);
                add = fmaf(wt1, kT[40 + d],  add);
                add = fmaf(wt2, kT[80 + d],  add);
                add = fmaf(wt3, kT[120 + d], add);
                Mr[d] = base + add;
            }
        }
        __syncthreads();

        // ---- J: read einsum -> rhT r-part ----
#pragma unroll
        for (int s = 0; s < 3; s++) {
            int i = tid + s * TPB;
            if (i < GB * R_ * D_) {
                int g = i / 160, j = i - g * 160;
                int r = j / 40, d = j - r * 40;
                const float* sw = S + OFF_SWR + g * 512 + r * 128;
                const float* Mc = S + OFF_SM + g * NSLOT * MSTR + d;
                float a0 = 0.f, a1 = 0.f, a2 = 0.f, a3 = 0.f;
                for (int n = 0; n < NSLOT; n += 4) {
                    a0 = fmaf(sw[n],     tf32r(Mc[(n)     * MSTR]), a0);
                    a1 = fmaf(sw[n + 1], tf32r(Mc[(n + 1) * MSTR]), a1);
                    a2 = fmaf(sw[n + 2], tf32r(Mc[(n + 2) * MSTR]), a2);
                    a3 = fmaf(sw[n + 3], tf32r(Mc[(n + 3) * MSTR]), a3);
                }
                float acc = (a0 + a1) + (a2 + a3);
                S[OFF_RHT + g * 361 + j] = tf32r(acc);
            }
        }
        __syncthreads();

        // ---- K: classifier (transposed Wc, coalesced) ----
        for (int o = warp; o < GB * C_; o += NW) {
            int g = o / C_, cl = o - g * C_;
            const float* rh = S + OFF_RHT + g * 361;
            const float* wc = g_WcT + cl * KRH;
            float acc = 0.f;
            for (int j = lane; j < KRH; j += 32) {
                float v = (j < H_) ? rh[R_*D_ + j] : rh[j - H_];
                acc = fmaf(v, wc[j], acc);
            }
#pragma unroll
            for (int o2 = 16; o2 > 0; o2 >>= 1) acc += __shfl_xor_sync(0xffffffffu, acc, o2);
            if (lane == 0) S[OFF_SLOG + o] = acc + bc[cl];
        }
        __syncthreads();

        // ---- L: probs + loss/acc rows — warp per group, exact R13 reduction order ----
        if (warp < GB) {
            int g = warp;
            int m = (bb + g) * T_ + t;
            float v = (lane < C_) ? S[OFF_SLOG + g * C_ + lane] : 0.f;
            float v0 = __shfl_sync(0xffffffffu, v, 0);
            float v1 = __shfl_sync(0xffffffffu, v, 1);
            float v2 = __shfl_sync(0xffffffffu, v, 2);
            float v3 = __shfl_sync(0xffffffffu, v, 3);
            float v4 = __shfl_sync(0xffffffffu, v, 4);
            float mx = v0; int am = 0;
            if (v1 > mx) { mx = v1; am = 1; }
            if (v2 > mx) { mx = v2; am = 2; }
            if (v3 > mx) { mx = v3; am = 3; }
            if (v4 > mx) { mx = v4; am = 4; }
            float e = exp_acc(v - mx);                    // parallel over lanes 0..4
            float e0 = __shfl_sync(0xffffffffu, e, 0);
            float e1 = __shfl_sync(0xffffffffu, e, 1);
            float e2 = __shfl_sync(0xffffffffu, e, 2);
            float e3 = __shfl_sync(0xffffffffu, e, 3);
            float e4 = __shfl_sync(0xffffffffu, e, 4);
            float ssum = ((((e0 + e1) + e2) + e3) + e4);  // exact ascending order
            float pr = __fdiv_rn(e, ssum);
            if (lane < C_) out[m * C_ + lane] = pr;
            float p0 = __shfl_sync(0xffffffffu, pr, 0);
            float p1 = __shfl_sync(0xffffffffu, pr, 1);
            float p2 = __shfl_sync(0xffffffffu, pr, 2);
            float p3 = __shfl_sync(0xffffffffu, pr, 3);
            float p4 = __shfl_sync(0xffffffffu, pr, 4);
            float mp = p0;
            mp = fmaxf(mp, p1); mp = fmaxf(mp, p2); mp = fmaxf(mp, p3); mp = fmaxf(mp, p4);
            float e2v = exp_acc(pr - mp);                 // parallel over lanes 0..4
            float q0 = __shfl_sync(0xffffffffu, e2v, 0);
            float q1 = __shfl_sync(0xffffffffu, e2v, 1);
            float q2 = __shfl_sync(0xffffffffu, e2v, 2);
            float q3 = __shfl_sync(0xffffffffu, e2v, 3);
            float q4 = __shfl_sync(0xffffffffu, e2v, 4);
            float se = ((((q0 + q1) + q2) + q3) + q4);    // exact ascending order
            if (lane == 0) {
                int lab = labels[m];
                float prl = (lab == 0) ? p0 : (lab == 1) ? p1 : (lab == 2) ? p2 : (lab == 3) ? p3 : p4;
                g_rowloss[m] = (float)(log((double)se)) + mp - prl;
                g_rowcorr[m] = (am == lab) ? 1.f : 0.f;
            }
        }
        __syncthreads();
    }
}

// ---------------- deterministic final reduction ----------------
__global__ __launch_bounds__(1024) void finalize_kernel(float* __restrict__ out) {
    __shared__ float sl[1024], sa[1024];
    int tid = threadIdx.x;
    float l = 0.f, a = 0.f;
    for (int i = tid; i < BT; i += 1024) { l += g_rowloss[i]; a += g_rowcorr[i]; }
    sl[tid] = l; sa[tid] = a;
    __syncthreads();
    for (int s = 512; s > 0; s >>= 1) {
        if (tid < s) { sl[tid] += sl[tid + s]; sa[tid] += sa[tid + s]; }
        __syncthreads();
    }
    if (tid == 0) {
        out[BT * C_]     = __fdiv_rn(sl[0], (float)BT);
        out[BT * C_ + 1] = __fdiv_rn(sa[0], (float)BT);
    }
}

// ---------------- launch ----------------
extern "C" void kernel_launch(void* const* d_in, const int* in_sizes, int n_in,
                              void* d_out, int out_size) {
    const float* images = (const float*)d_in[0];
    const int*   labels = (const int*)d_in[1];
    const float* Wx     = (const float*)d_in[2];
    const float* Wh     = (const float*)d_in[3];
    const float* b_lstm = (const float*)d_in[4];
    const float* Wp     = (const float*)d_in[5];
    const float* bp     = (const float*)d_in[6];
    const float* Wc     = (const float*)d_in[7];
    const float* bc     = (const float*)d_in[8];
    float* out = (float*)d_out;

    float* pXpre;
    cudaGetSymbolAddress((void**)&pXpre, g_Xpre);

    cudaFuncSetAttribute(fused_kernel, cudaFuncAttributeMaxDynamicSharedMemorySize, SMEM_BYTES);
    cudaFuncSetAttribute(gemm0_kernel, cudaFuncAttributeMaxDynamicSharedMemorySize, G0_SMEM_FLOATS * 4);

    init_kernel<<<320, 256>>>(Wx, Wh, Wp, Wc);

    {
        dim3 grid(5, BT / 128);    // N=800 -> 5 tiles of 160
        gemm0_kernel<<<grid, 256, G0_SMEM_FLOATS * 4>>>(images, Wx, b_lstm, labels, pXpre);
    }

    fused_kernel<<<NBLK, TPB, SMEM_BYTES>>>(bp, bc, labels, out);

    finalize_kernel<<<1, 1024>>>(out);
}

// round 15
// speedup vs baseline: 1.0154x; 1.0154x over previous
#include <cuda_runtime.h>
#include <math.h>
#include <stdint.h>

#define B_   1024
#define T_   50
#define IN_  784
#define NSLOT 128
#define D_   40
#define H_   200
#define R_   4
#define C_   5
#define G4H  800
#define KRH  360
#define BT   (B_*T_)
#define GB   8            // batches per block
#define NBLK (B_/GB)      // 128
#define TPB  512
#define NW   (TPB/32)     // 16 warps
#define MSTR 41           // padded M row stride (conflict-free)

// ---------------- device globals ----------------
__device__ float g_Xpre[BT * G4H];                   // images@Wx + b + offset row (fp32)
__device__ __align__(16) uint32_t g_W4P[50*45*96];   // 24-bit packed tf32 Wrh (lossless)
__device__ __align__(16) float g_WpM[21*25*64];      // mma-fragment tf32 Wp (float2/lane)
__device__ float g_WcT[C_ * KRH];                    // tf32-rounded Wc, TRANSPOSED [C][KRH]
__device__ __align__(16) float g_Wxr[IN_ * G4H];     // tf32-rounded Wx rows [0,784)
__device__ float g_rowloss[BT];
__device__ float g_rowcorr[BT];

__device__ __forceinline__ float tf32r(float x) {
    float y;
    asm("cvt.rna.tf32.f32 %0, %1;" : "=f"(y) : "f"(x));
    return y;
}

// ---------------- precise transcendentals (fast-math immune) ----------------
__device__ __forceinline__ float exp_acc(float x) {
    x = fminf(fmaxf(x, -87.0f), 88.0f);
    float n = rintf(x * 1.44269504088896341f);
    float r = fmaf(n, -0.693359375f, x);
    r = fmaf(n, 2.12194440e-4f, r);
    float z = r * r;
    float p = 1.9875691500e-4f;
    p = fmaf(p, r, 1.3981999507e-3f);
    p = fmaf(p, r, 8.3334519073e-3f);
    p = fmaf(p, r, 4.1665795894e-2f);
    p = fmaf(p, r, 1.6666665459e-1f);
    p = fmaf(p, r, 5.0000001201e-1f);
    float res = fmaf(p, z, r) + 1.0f;
    int i = (int)n;
    float scale = __int_as_float((i + 127) << 23);
    return res * scale;
}
__device__ __forceinline__ float expm1_small(float y) {
    float p = 2.7557319e-7f;
    p = fmaf(p, y, 2.4801587e-5f);
    p = fmaf(p, y, 1.9841270e-4f);
    p = fmaf(p, y, 1.3888889e-3f);
    p = fmaf(p, y, 8.3333333e-3f);
    p = fmaf(p, y, 4.1666667e-2f);
    p = fmaf(p, y, 1.6666667e-1f);
    p = fmaf(p, y, 0.5f);
    p = fmaf(p, y, 1.0f);
    return y * p;
}
__device__ __forceinline__ float tanh_acc(float x) {
    float a = fabsf(x);
    float t;
    if (a < 0.51f) {
        float em1 = expm1_small(2.0f * a);
        t = __fdiv_rn(em1, em1 + 2.0f);
    } else if (a < 9.1f) {
        float e = exp_acc(2.0f * a);
        t = 1.0f - __fdiv_rn(2.0f, e + 1.0f);
    } else {
        t = 1.0f;
    }
    return copysignf(t, x);
}
__device__ __forceinline__ float sigm(float x) {
    float e = exp_acc(-x);
    return __fdiv_rn(1.0f, 1.0f + e);
}

// ---------------- init: build packed / pre-rounded weights ----------------
__global__ void init_kernel(const float* __restrict__ Wx, const float* __restrict__ Wh,
                            const float* __restrict__ Wp, const float* __restrict__ Wc) {
    int idx = blockIdx.x * blockDim.x + threadIdx.x;
    int stride = gridDim.x * blockDim.x;
    for (int i = idx; i < 50*45*32; i += stride) {
        int lane = i & 31;
        int k8 = (i >> 5) % 45;
        int p = (i >> 5) / 45;
        int lr = lane >> 2, lc = lane & 3;
        uint32_t vb[4];
#pragma unroll
        for (int q = 0; q < 4; q++) {
            int row = k8 * 8 + (q & 1) * 4 + lc;
            int col = p * 16 + (q >> 1) * 8 + lr;
            float v = (row < R_*D_) ? Wx[(size_t)(IN_ + C_ + row) * G4H + col]
                                    : Wh[(size_t)(row - R_*D_) * G4H + col];
            vb[q] = __float_as_uint(tf32r(v));
        }
        uint32_t a = vb[0], b = vb[1], c = vb[2], d = vb[3];
        uint32_t u0 = (a >> 8) | (b << 16);
        uint32_t u1 = (b >> 16) | ((c >> 8) << 16);
        uint32_t u2 = (c >> 24) | (d & 0xFFFFFF00u);
        int base = (p * 45 + k8) * 96 + lane;
        g_W4P[base]      = u0;
        g_W4P[base + 32] = u1;
        g_W4P[base + 64] = u2;
    }
    for (int i = idx; i < 21*25*32; i += stride) {
        int lane = i & 31;
        int k8 = (i >> 5) % 25;
        int q = (i >> 5) / 25;
        int lr = lane >> 2, lc = lane & 3;
        int col = q * 8 + lr;
        int row0 = k8 * 8 + lc, row1 = row0 + 4;
        float b0 = (col < 164) ? tf32r(Wp[row0 * 164 + col]) : 0.f;
        float b1 = (col < 164) ? tf32r(Wp[row1 * 164 + col]) : 0.f;
        int base = ((q * 25 + k8) * 32 + lane) * 2;
        g_WpM[base]     = b0;
        g_WpM[base + 1] = b1;
    }
    for (int i = idx; i < KRH * C_; i += stride) {
        int j = i / C_, cl = i - (i / C_) * C_;
        g_WcT[cl * KRH + j] = tf32r(Wc[i]);
    }
    for (int i = idx; i < IN_ * G4H; i += stride) g_Wxr[i] = tf32r(Wx[i]);
}

// ---------------- tf32 mma helper ----------------
__device__ __forceinline__ void mma_tf32(float& c0, float& c1, float& c2, float& c3,
                                         uint32_t a0, uint32_t a1, uint32_t a2, uint32_t a3,
                                         uint32_t b0, uint32_t b1) {
    asm volatile(
        "mma.sync.aligned.m16n8k8.row.col.f32.tf32.tf32.f32 "
        "{%0,%1,%2,%3}, {%4,%5,%6,%7}, {%8,%9}, {%0,%1,%2,%3};\n"
        : "+f"(c0), "+f"(c1), "+f"(c2), "+f"(c3)
        : "r"(a0), "r"(a1), "r"(a2), "r"(a3), "r"(b0), "r"(b1));
}

// ---------------- gemm0: Xpre = images @ Wx[:784] + b + offset row  (BM=128,BN=128) -------
#define NKT 25
#define G0_SMEM_FLOATS (2*128*36 + 2*32*132)    // 17664
__global__ __launch_bounds__(256) void gemm0_kernel(
    const float* __restrict__ A, const float* __restrict__ WxFull,
    const float* __restrict__ b_lstm, const int* __restrict__ labs,
    float* __restrict__ Cout)
{
    extern __shared__ float SG[];
    float* As = SG;            // [2][128][36]
    float* Bs = SG + 9216;     // [2][32][132]
    int tid = threadIdx.x, lane = tid & 31, warp = tid >> 5;
    int wm = warp >> 2, wn = warp & 3;
    int m0 = blockIdx.y * 128, n0 = blockIdx.x * 128;
    int lr = lane >> 2, lc = lane & 3;
    float c[4][4][4];
#pragma unroll
    for (int i = 0; i < 4; i++)
#pragma unroll
        for (int j = 0; j < 4; j++)
#pragma unroll
            for (int q = 0; q < 4; q++) c[i][j][q] = 0.f;

#define G0_ISSUE(IT) do {                                                       \
    int st_ = (IT) & 1;                                                         \
    int k0_ = (IT) * 32;                                                        \
    _Pragma("unroll")                                                           \
    for (int i_ = 0; i_ < 4; i_++) {                                            \
        int e_ = tid + i_ * 256;                                                \
        int row_ = e_ >> 3, c4_ = (e_ & 7) * 4;                                 \
        uint32_t sz_ = (k0_ + c4_ + 3 < IN_) ? 16u : 0u;                        \
        const float* src_ = A + (size_t)(m0 + row_) * IN_ + (sz_ ? (k0_ + c4_) : 0); \
        uint32_t da_ = (uint32_t)__cvta_generic_to_shared(&As[st_*4608 + row_*36 + c4_]); \
        asm volatile("cp.async.ca.shared.global [%0], [%1], 16, %2;" :: "r"(da_), "l"(src_), "r"(sz_)); \
    }                                                                           \
    _Pragma("unroll")                                                           \
    for (int i_ = 0; i_ < 4; i_++) {                                            \
        int e_ = tid + i_ * 256;                                                \
        int row_ = e_ >> 5, c4_ = (e_ & 31) * 4;                                \
        int krow_ = k0_ + row_;                                                 \
        int col_ = n0 + c4_;                                                    \
        uint32_t sz_ = (krow_ < IN_ && col_ + 3 < G4H) ? 16u : 0u;              \
        const float* src_ = g_Wxr + (sz_ ? ((size_t)krow_ * G4H + col_) : 0);   \
        uint32_t da_ = (uint32_t)__cvta_generic_to_shared(&Bs[st_*4224 + row_*132 + c4_]); \
        asm volatile("cp.async.ca.shared.global [%0], [%1], 16, %2;" :: "r"(da_), "l"(src_), "r"(sz_)); \
    }                                                                           \
    asm volatile("cp.async.commit_group;");                                     \
} while (0)

    G0_ISSUE(0);
    for (int it = 0; it < NKT; it++) {
        if (it + 1 < NKT) {
            G0_ISSUE(it + 1);
            asm volatile("cp.async.wait_group 1;");
        } else {
            asm volatile("cp.async.wait_group 0;");
        }
        __syncthreads();
        int st = it & 1;
        const float* Ast = As + st * 4608;
        const float* Bst = Bs + st * 4224;
#pragma unroll
        for (int k8 = 0; k8 < 4; k8++) {
            int kk = k8 * 8;
            uint32_t a[4][4];
#pragma unroll
            for (int mt = 0; mt < 4; mt++) {
                int arow = wm * 64 + mt * 16 + lr;
                a[mt][0] = __float_as_uint(tf32r(Ast[arow*36 + kk + lc]));
                a[mt][1] = __float_as_uint(tf32r(Ast[(arow + 8)*36 + kk + lc]));
                a[mt][2] = __float_as_uint(tf32r(Ast[arow*36 + kk + lc + 4]));
                a[mt][3] = __float_as_uint(tf32r(Ast[(arow + 8)*36 + kk + lc + 4]));
            }
#pragma unroll
            for (int nt = 0; nt < 4; nt++) {
                int bcol = wn * 32 + nt * 8 + lr;
                uint32_t b0 = __float_as_uint(Bst[(kk + lc)*132 + bcol]);
                uint32_t b1 = __float_as_uint(Bst[(kk + lc + 4)*132 + bcol]);
#pragma unroll
                for (int mt = 0; mt < 4; mt++)
                    mma_tf32(c[mt][nt][0], c[mt][nt][1], c[mt][nt][2], c[mt][nt][3],
                             a[mt][0], a[mt][1], a[mt][2], a[mt][3], b0, b1);
            }
        }
        __syncthreads();
    }

#pragma unroll
    for (int mt = 0; mt < 4; mt++) {
        int row0 = m0 + wm * 64 + mt * 16 + lr;
#pragma unroll
        for (int rr = 0; rr < 2; rr++) {
            int row = row0 + rr * 8;
            int tt = row % T_;
            int lab = (tt > 0) ? labs[row - 1] : 0;
#pragma unroll
            for (int nt = 0; nt < 4; nt++) {
                int col = n0 + wn * 32 + nt * 8 + 2 * lc;
#pragma unroll
                for (int cc = 0; cc < 2; cc++) {
                    int cg = col + cc;
                    if (cg < G4H) {
                        float v = c[mt][nt][rr * 2 + cc];
                        v += b_lstm[cg];
                        if (tt > 0) v += tf32r(WxFull[(size_t)(IN_ + lab) * G4H + cg]);
                        Cout[(size_t)row * G4H + cg] = v;
                    }
                }
            }
        }
    }
}

// ---------------- fused persistent recurrence kernel (R13 + fused KL, 2 fewer barriers) ---
#define OFF_SM   0                      // GB*5248 = 41984
#define OFF_RHT  41984                  // GB*361 = 2888 -> 44872
#define OFF_GU   44872                  // 6400 gates; union: SWR+MN+SKN
#define OFF_SWR  (OFF_GU)               // 4096
#define OFF_MN   (OFF_GU + 4096)        // 1024
#define OFF_SKN  (OFF_GU + 5120)        // 1280
#define OFF_WRO  51272                  // 4096 -> 55368
#define OFF_WU   55368                  // 1024 -> 56392
#define OFF_SKT  56392                  // 1280 -> 57672
#define OFF_KN   57672                  // 32
#define OFF_SSIG 57704                  // 32
#define OFF_SLOG 57736                  // 40 (unused now)
#define OFF_LU   57776                  // 32 ints
#define SMEM_FLOATS 57808
#define SMEM_BYTES  (SMEM_FLOATS * 4)   // 231232 <= 232448

__global__ __launch_bounds__(TPB, 1) void fused_kernel(
    const float* __restrict__ bp, const float* __restrict__ bc,
    const int* __restrict__ labels, float* __restrict__ out)
{
    extern __shared__ float S[];
    int tid = threadIdx.x;
    int lane = tid & 31, warp = tid >> 5;
    int bb = blockIdx.x * GB;
    int* s_luI = (int*)(S + OFF_LU);
    const int lr = lane >> 2, lc = lane & 3;

    float c_reg[4] = {0.f, 0.f, 0.f, 0.f};

    // ---- state init ----
    for (int i = tid; i < GB * NSLOT * MSTR; i += TPB) S[OFF_SM + i] = 1e-6f;
    for (int i = tid; i < GB * 361; i += TPB) {
        int j = i % 361;
        S[OFF_RHT + i] = (j < R_*D_) ? tf32r(1e-6f) : 0.f;
    }
    for (int i = tid; i < GB * NSLOT; i += TPB) S[OFF_WU + i] = ((i & 127) == 0) ? 1.f : 0.f;
    for (int i = tid; i < GB * 512; i += TPB)   S[OFF_WRO + i] = ((i & 127) == 0) ? 1.f : 0.f;
    __syncthreads();

    for (int t = 0; t < T_; t++) {
        // ---- A: gates GEMM [8x360]@[360x800] via mma + 24-bit packed W, + Xpre epilogue ----
        // (safe to enter without a barrier after KL: A writes GU which KL never reads,
        //  and both only READ rhT)
        {
            const float* rhRow = S + OFF_RHT + lr * 361;
            for (int p = warp; p < 50; p += NW) {
                float c00 = 0.f, c01 = 0.f, c02 = 0.f, c03 = 0.f;
                float c10 = 0.f, c11 = 0.f, c12 = 0.f, c13 = 0.f;
                const uint32_t* wp = g_W4P + p * (45 * 96) + lane;
#pragma unroll 5
                for (int k8 = 0; k8 < 45; k8++) {
                    uint32_t u0 = wp[0], u1 = wp[32], u2 = wp[64];
                    wp += 96;
                    uint32_t wx = u0 << 8;
                    uint32_t wy = ((u0 >> 24) << 8) | (u1 << 16);
                    uint32_t wz = ((u1 >> 16) << 8) | (u2 << 24);
                    uint32_t ww = u2 & 0xFFFFFF00u;
                    uint32_t a0 = __float_as_uint(rhRow[k8 * 8 + lc]);
                    uint32_t a2 = __float_as_uint(rhRow[k8 * 8 + 4 + lc]);
                    mma_tf32(c00, c01, c02, c03, a0, 0u, a2, 0u, wx, wy);
                    mma_tf32(c10, c11, c12, c13, a0, 0u, a2, 0u, wz, ww);
                }
                int col0 = p * 16 + 2 * lc;
                const float* xp = g_Xpre + ((size_t)(bb + lr) * T_ + t) * G4H;
                float* gr = S + OFF_GU + lr * 800;
                gr[col0]     = c00 + xp[col0];
                gr[col0 + 1] = c01 + xp[col0 + 1];
                gr[col0 + 8] = c10 + xp[col0 + 8];
                gr[col0 + 9] = c11 + xp[col0 + 9];
            }
        }
        __syncthreads();

        // ---- B: LSTM pointwise ----
#pragma unroll
        for (int s = 0; s < 4; s++) {
            int i = tid + s * TPB;
            if (i < GB * H_) {
                int g = i / H_, u = i - g * H_;
                const float* gg = S + OFF_GU + g * 800;
                float ig = gg[u], fg = gg[200 + u], gz = gg[400 + u], og = gg[600 + u];
                float c_new = sigm(fg) * c_reg[s] + sigm(ig) * tanh_acc(gz);
                c_reg[s] = c_new;
                float h = sigm(og) * tanh_acc(c_new);
                S[OFF_RHT + g * 361 + R_*D_ + u] = tf32r(h);
            }
        }
        __syncthreads();

        // ---- C: keys via mma [8x200]@[200x164] + M row norms ----
        {
            const float* hRow = S + OFF_RHT + lr * 361 + R_*D_;
            for (int q = warp; q < 21; q += NW) {
                float k0v = 0.f, k1v = 0.f, k2d = 0.f, k3d = 0.f;
                const float2* wp2 = reinterpret_cast<const float2*>(g_WpM) + (q * 25) * 32 + lane;
#pragma unroll 5
                for (int k8 = 0; k8 < 25; k8++) {
                    float2 b = wp2[k8 * 32];
                    uint32_t a0 = __float_as_uint(hRow[k8 * 8 + lc]);
                    uint32_t a2 = __float_as_uint(hRow[k8 * 8 + 4 + lc]);
                    mma_tf32(k0v, k1v, k2d, k3d, a0, 0u, a2, 0u,
                             __float_as_uint(b.x), __float_as_uint(b.y));
                }
                int g = lr;
#pragma unroll
                for (int cc = 0; cc < 2; cc++) {
                    int j = q * 8 + 2 * lc + cc;
                    if (j < 164) {
                        float acc = (cc ? k1v : k0v) + bp[j];
                        int r = j / 41, w = j - r * 41;
                        if (w < D_) S[OFF_SKT + g * 160 + r * 40 + w] = tanh_acc(acc);
                        else        S[OFF_SSIG + g * 4 + r] = sigm(acc);
                    }
                }
            }
        }
#pragma unroll
        for (int s = 0; s < 2; s++) {
            int p = tid + s * TPB;
            int g = p >> 7, n = p & 127;
            const float* Mr = S + OFF_SM + g * NSLOT * MSTR + n * MSTR;
            float ss = 0.f;
            for (int d = 0; d < D_; d++) ss = fmaf(Mr[d], Mr[d], ss);
            S[OFF_MN + p] = __fsqrt_rn(ss) + 1e-8f;
        }
        __syncthreads();

        // ---- D: key norms (tid<32) + LU selection (warps 8..15) ----
        if (tid < 32) {
            int g = tid >> 2, r = tid & 3;
            const float* kk = S + OFF_SKT + g * 160 + r * 40;
            float ss = 0.f;
            for (int d = 0; d < D_; d++) ss = fmaf(kk[d], kk[d], ss);
            S[OFF_KN + tid] = __fsqrt_rn(ss) + 1e-8f;
        } else if (warp >= 8 && warp < 16) {
            int g = warp - 8;
            const float* wu = S + OFF_WU + g * NSLOT;
            float v0 = wu[lane], v1 = wu[lane + 32], v2 = wu[lane + 64], v3 = wu[lane + 96];
            int i0 = lane, i1 = lane + 32, i2 = lane + 64, i3 = lane + 96;
#pragma unroll
            for (int s = 0; s < R_; s++) {
                float bv = v0; int bi = i0;
                if (v1 < bv || (v1 == bv && i1 < bi)) { bv = v1; bi = i1; }
                if (v2 < bv || (v2 == bv && i2 < bi)) { bv = v2; bi = i2; }
                if (v3 < bv || (v3 == bv && i3 < bi)) { bv = v3; bi = i3; }
#pragma unroll
                for (int o = 16; o > 0; o >>= 1) {
                    float ov = __shfl_xor_sync(0xffffffffu, bv, o);
                    int   oi = __shfl_xor_sync(0xffffffffu, bi, o);
                    if (ov < bv || (ov == bv && oi < bi)) { bv = ov; bi = oi; }
                }
                if (lane == 0) s_luI[g * 4 + s] = bi;
                if      (bi == i0) v0 = 3.0e38f;
                else if (bi == i1) v1 = 3.0e38f;
                else if (bi == i2) v2 = 3.0e38f;
                else if (bi == i3) v3 = 3.0e38f;
            }
        }
        __syncthreads();

        // ---- E: round keys; build skn ----
#pragma unroll
        for (int s = 0; s < 3; s++) {
            int i = tid + s * TPB;
            if (i < GB * 160) {
                int g = i / 160, j = i - g * 160;
                int r = j / 40;
                float raw = S[OFF_SKT + i];
                float nrm = S[OFF_KN + g * 4 + r];
                S[OFF_SKN + i] = tf32r(__fdiv_rn(raw, nrm));
                S[OFF_SKT + i] = tf32r(raw);
            }
        }
        __syncthreads();

        // ---- F: cosine logits ----
#pragma unroll
        for (int s = 0; s < 2; s++) {
            int p = tid + s * TPB;
            int g = p >> 7, n = p & 127;
            const float* Mr = S + OFF_SM + g * NSLOT * MSTR + n * MSTR;
            const float* kn = S + OFF_SKN + g * 160;
            float rinv = __fdiv_rn(1.f, S[OFF_MN + p]);
            float a0 = 0.f, a1 = 0.f, a2 = 0.f, a3 = 0.f;
            for (int d = 0; d < D_; d++) {
                float mn = tf32r(Mr[d] * rinv);
                a0 = fmaf(mn, kn[d],       a0);
                a1 = fmaf(mn, kn[40 + d],  a1);
                a2 = fmaf(mn, kn[80 + d],  a2);
                a3 = fmaf(mn, kn[120 + d], a3);
            }
            float* sw = S + OFF_SWR + g * 512;
            sw[n] = a0; sw[128 + n] = a1; sw[256 + n] = a2; sw[384 + n] = a3;
        }
        __syncthreads();

        // ---- G: softmax per (g,r) ----
        for (int row = warp; row < GB * R_; row += NW) {
            int g = row >> 2, r = row & 3;
            float* sw = S + OFF_SWR + g * 512 + r * 128;
            float v0 = sw[lane], v1 = sw[lane + 32], v2 = sw[lane + 64], v3 = sw[lane + 96];
            float mx = fmaxf(fmaxf(v0, v1), fmaxf(v2, v3));
            for (int o = 16; o > 0; o >>= 1) mx = fmaxf(mx, __shfl_xor_sync(0xffffffffu, mx, o));
            float e0 = exp_acc(v0 - mx), e1 = exp_acc(v1 - mx), e2 = exp_acc(v2 - mx), e3 = exp_acc(v3 - mx);
            float ssum = e0 + e1 + e2 + e3;
            for (int o = 16; o > 0; o >>= 1) ssum += __shfl_xor_sync(0xffffffffu, ssum, o);
            sw[lane]      = __fdiv_rn(e0, ssum);
            sw[lane + 32] = __fdiv_rn(e1, ssum);
            sw[lane + 64] = __fdiv_rn(e2, ssum);
            sw[lane + 96] = __fdiv_rn(e3, ssum);
        }
        __syncthreads();

        // ---- H: usage update + wrOld<-swr + memory write + round swr in place ----
#pragma unroll
        for (int s = 0; s < 2; s++) {
            int p = tid + s * TPB;
            int g = p >> 7, n = p & 127;
            float* wro = S + OFF_WRO + g * 512;
            float* sw  = S + OFF_SWR + g * 512;
            int lu0 = s_luI[g*4], lu1 = s_luI[g*4+1], lu2 = s_luI[g*4+2], lu3 = s_luI[g*4+3];
            float wlu = (n == lu0 || n == lu1 || n == lu2 || n == lu3) ? 1.f : 0.f;
            float sg0 = S[OFF_SSIG + g*4], sg1 = S[OFF_SSIG + g*4+1];
            float sg2 = S[OFF_SSIG + g*4+2], sg3 = S[OFF_SSIG + g*4+3];
            float wo0 = wro[n], wo1 = wro[128+n], wo2 = wro[256+n], wo3 = wro[384+n];
            float ww0 = sg0 * wo0 + (1.f - sg0) * wlu;
            float ww1 = sg1 * wo1 + (1.f - sg1) * wlu;
            float ww2 = sg2 * wo2 + (1.f - sg2) * wlu;
            float ww3 = sg3 * wo3 + (1.f - sg3) * wlu;
            float sr0 = sw[n], sr1 = sw[128+n], sr2 = sw[256+n], sr3 = sw[384+n];
            float v = 0.95f * S[OFF_WU + p];
            v += sr0 + ww0; v += sr1 + ww1; v += sr2 + ww2; v += sr3 + ww3;
            S[OFF_WU + p] = v;
            wro[n] = sr0; wro[128+n] = sr1; wro[256+n] = sr2; wro[384+n] = sr3;
            sw[n] = tf32r(sr0); sw[128+n] = tf32r(sr1); sw[256+n] = tf32r(sr2); sw[384+n] = tf32r(sr3);
            float wt0 = tf32r(ww0), wt1 = tf32r(ww1), wt2 = tf32r(ww2), wt3 = tf32r(ww3);
            float* Mr = S + OFF_SM + g * NSLOT * MSTR + n * MSTR;
            const float* kT = S + OFF_SKT + g * 160;
            bool zero_base = (n == lu3);
            for (int d = 0; d < D_; d++) {
                float base = zero_base ? 0.f : Mr[d];
                float add = 0.f;
                add = fmaf(wt0, kT[d],       add);
                add = fmaf(wt1, kT[40 + d],  add);
                add = fmaf(wt2, kT[80 + d],  add);
                add = fmaf(wt3, kT[120 + d], add);
                Mr[d] = base + add;
            }
        }
        __syncthreads();

        // ---- J: read einsum -> rhT r-part ----
#pragma unroll
        for (int s = 0; s < 3; s++) {
            int i = tid + s * TPB;
            if (i < GB * R_ * D_) {
                int g = i / 160, j = i - g * 160;
                int r = j / 40, d = j - r * 40;
                const float* sw = S + OFF_SWR + g * 512 + r * 128;
                const float* Mc = S + OFF_SM + g * NSLOT * MSTR + d;
                float a0 = 0.f, a1 = 0.f, a2 = 0.f, a3 = 0.f;
                for (int n = 0; n < NSLOT; n += 4) {
                    a0 = fmaf(sw[n],     tf32r(Mc[(n)     * MSTR]), a0);
                    a1 = fmaf(sw[n + 1], tf32r(Mc[(n + 1) * MSTR]), a1);
                    a2 = fmaf(sw[n + 2], tf32r(Mc[(n + 2) * MSTR]), a2);
                    a3 = fmaf(sw[n + 3], tf32r(Mc[(n + 3) * MSTR]), a3);
                }
                float acc = (a0 + a1) + (a2 + a3);
                S[OFF_RHT + g * 361 + j] = tf32r(acc);
            }
        }
        __syncthreads();

        // ---- KL: classifier + probs/loss fused; warp g handles group g; NO trailing barrier ----
        if (warp < GB) {
            int g = warp;
            int m = (bb + g) * T_ + t;
            const float* rh = S + OFF_RHT + g * 361;
            float lg[C_];
#pragma unroll
            for (int cl = 0; cl < C_; cl++) {
                const float* wc = g_WcT + cl * KRH;
                float acc = 0.f;
                for (int j = lane; j < KRH; j += 32) {
                    float v = (j < H_) ? rh[R_*D_ + j] : rh[j - H_];
                    acc = fmaf(v, wc[j], acc);
                }
#pragma unroll
                for (int o2 = 16; o2 > 0; o2 >>= 1) acc += __shfl_xor_sync(0xffffffffu, acc, o2);
                lg[cl] = acc + bc[cl];     // butterfly reduce -> identical in all lanes
            }
            // L: exact R13 serial order, replicated across lanes
            float mx = lg[0]; int am = 0;
#pragma unroll
            for (int c = 1; c < C_; c++) if (lg[c] > mx) { mx = lg[c]; am = c; }
            float e[C_], ssum = 0.f;
#pragma unroll
            for (int c = 0; c < C_; c++) { e[c] = exp_acc(lg[c] - mx); ssum += e[c]; }
            float pr[C_];
#pragma unroll
            for (int c = 0; c < C_; c++) pr[c] = __fdiv_rn(e[c], ssum);
            if (lane < C_) out[m * C_ + lane] = pr[lane];
            if (lane == 0) {
                float mp = pr[0];
#pragma unroll
                for (int c = 1; c < C_; c++) mp = fmaxf(mp, pr[c]);
                float se = 0.f;
#pragma unroll
                for (int c = 0; c < C_; c++) se += exp_acc(pr[c] - mp);
                int lab = labels[m];
                g_rowloss[m] = (float)(log((double)se)) + mp - pr[lab];
                g_rowcorr[m] = (am == lab) ? 1.f : 0.f;
            }
        }
        // no __syncthreads(): next-iteration phase A writes GU (never read by KL)
        // and both phases only read rhT; warps 8..15 start the next GEMM immediately.
    }
}

// ---------------- deterministic final reduction ----------------
__global__ __launch_bounds__(1024) void finalize_kernel(float* __restrict__ out) {
    __shared__ float sl[1024], sa[1024];
    int tid = threadIdx.x;
    float l = 0.f, a = 0.f;
    for (int i = tid; i < BT; i += 1024) { l += g_rowloss[i]; a += g_rowcorr[i]; }
    sl[tid] = l; sa[tid] = a;
    __syncthreads();
    for (int s = 512; s > 0; s >>= 1) {
        if (tid < s) { sl[tid] += sl[tid + s]; sa[tid] += sa[tid + s]; }
        __syncthreads();
    }
    if (tid == 0) {
        out[BT * C_]     = __fdiv_rn(sl[0], (float)BT);
        out[BT * C_ + 1] = __fdiv_rn(sa[0], (float)BT);
    }
}

// ---------------- launch ----------------
extern "C" void kernel_launch(void* const* d_in, const int* in_sizes, int n_in,
                              void* d_out, int out_size) {
    const float* images = (const float*)d_in[0];
    const int*   labels = (const int*)d_in[1];
    const float* Wx     = (const float*)d_in[2];
    const float* Wh     = (const float*)d_in[3];
    const float* b_lstm = (const float*)d_in[4];
    const float* Wp     = (const float*)d_in[5];
    const float* bp     = (const float*)d_in[6];
    const float* Wc     = (const float*)d_in[7];
    const float* bc     = (const float*)d_in[8];
    float* out = (float*)d_out;

    float* pXpre;
    cudaGetSymbolAddress((void**)&pXpre, g_Xpre);

    cudaFuncSetAttribute(fused_kernel, cudaFuncAttributeMaxDynamicSharedMemorySize, SMEM_BYTES);
    cudaFuncSetAttribute(gemm0_kernel, cudaFuncAttributeMaxDynamicSharedMemorySize, G0_SMEM_FLOATS * 4);

    init_kernel<<<320, 256>>>(Wx, Wh, Wp, Wc);

    {
        dim3 grid(7, BT / 128);
        gemm0_kernel<<<grid, 256, G0_SMEM_FLOATS * 4>>>(images, Wx, b_lstm, labels, pXpre);
    }

    fused_kernel<<<NBLK, TPB, SMEM_BYTES>>>(bp, bc, labels, out);

    finalize_kernel<<<1, 1024>>>(out);
}

// round 16
// speedup vs baseline: 1.1115x; 1.0947x over previous
#include <cuda_runtime.h>
#include <math.h>
#include <stdint.h>

#define B_   1024
#define T_   50
#define IN_  784
#define NSLOT 128
#define D_   40
#define H_   200
#define R_   4
#define C_   5
#define G4H  800
#define KRH  360
#define BT   (B_*T_)
#define GB   8            // batches per block
#define NBLK (B_/GB)      // 128
#define TPB  512
#define NW   (TPB/32)     // 16 warps
#define MSTR 41           // padded M row stride (conflict-free)

// ---------------- device globals ----------------
__device__ float g_Xpre[BT * G4H];                   // images@Wx + b + offset row (fp32)
__device__ __align__(16) uint32_t g_W4P[50*45*96];   // 24-bit packed tf32 Wrh (lossless)
__device__ __align__(16) float g_WpM[21*25*64];      // mma-fragment tf32 Wp (float2/lane)
__device__ float g_WcT[C_ * KRH];                    // tf32-rounded Wc, TRANSPOSED [C][KRH]
__device__ __align__(16) float g_Wxr[IN_ * G4H];     // tf32-rounded Wx rows [0,784)
__device__ float g_rowloss[BT];
__device__ float g_rowcorr[BT];

__device__ __forceinline__ float tf32r(float x) {
    float y;
    asm("cvt.rna.tf32.f32 %0, %1;" : "=f"(y) : "f"(x));
    return y;
}

// ---------------- precise transcendentals (fast-math immune) ----------------
__device__ __forceinline__ float exp_acc(float x) {
    x = fminf(fmaxf(x, -87.0f), 88.0f);
    float n = rintf(x * 1.44269504088896341f);
    float r = fmaf(n, -0.693359375f, x);
    r = fmaf(n, 2.12194440e-4f, r);
    float z = r * r;
    float p = 1.9875691500e-4f;
    p = fmaf(p, r, 1.3981999507e-3f);
    p = fmaf(p, r, 8.3334519073e-3f);
    p = fmaf(p, r, 4.1665795894e-2f);
    p = fmaf(p, r, 1.6666665459e-1f);
    p = fmaf(p, r, 5.0000001201e-1f);
    float res = fmaf(p, z, r) + 1.0f;
    int i = (int)n;
    float scale = __int_as_float((i + 127) << 23);
    return res * scale;
}
__device__ __forceinline__ float expm1_small(float y) {
    float p = 2.7557319e-7f;
    p = fmaf(p, y, 2.4801587e-5f);
    p = fmaf(p, y, 1.9841270e-4f);
    p = fmaf(p, y, 1.3888889e-3f);
    p = fmaf(p, y, 8.3333333e-3f);
    p = fmaf(p, y, 4.1666667e-2f);
    p = fmaf(p, y, 1.6666667e-1f);
    p = fmaf(p, y, 0.5f);
    p = fmaf(p, y, 1.0f);
    return y * p;
}
__device__ __forceinline__ float tanh_acc(float x) {
    float a = fabsf(x);
    float t;
    if (a < 0.51f) {
        float em1 = expm1_small(2.0f * a);
        t = __fdiv_rn(em1, em1 + 2.0f);
    } else if (a < 9.1f) {
        float e = exp_acc(2.0f * a);
        t = 1.0f - __fdiv_rn(2.0f, e + 1.0f);
    } else {
        t = 1.0f;
    }
    return copysignf(t, x);
}
__device__ __forceinline__ float sigm(float x) {
    float e = exp_acc(-x);
    return __fdiv_rn(1.0f, 1.0f + e);
}

// ---------------- init: build packed / pre-rounded weights ----------------
__global__ void init_kernel(const float* __restrict__ Wx, const float* __restrict__ Wh,
                            const float* __restrict__ Wp, const float* __restrict__ Wc) {
    int idx = blockIdx.x * blockDim.x + threadIdx.x;
    int stride = gridDim.x * blockDim.x;
    for (int i = idx; i < 50*45*32; i += stride) {
        int lane = i & 31;
        int k8 = (i >> 5) % 45;
        int p = (i >> 5) / 45;
        int lr = lane >> 2, lc = lane & 3;
        uint32_t vb[4];
#pragma unroll
        for (int q = 0; q < 4; q++) {
            int row = k8 * 8 + (q & 1) * 4 + lc;
            int col = p * 16 + (q >> 1) * 8 + lr;
            float v = (row < R_*D_) ? Wx[(size_t)(IN_ + C_ + row) * G4H + col]
                                    : Wh[(size_t)(row - R_*D_) * G4H + col];
            vb[q] = __float_as_uint(tf32r(v));
        }
        uint32_t a = vb[0], b = vb[1], c = vb[2], d = vb[3];
        uint32_t u0 = (a >> 8) | (b << 16);
        uint32_t u1 = (b >> 16) | ((c >> 8) << 16);
        uint32_t u2 = (c >> 24) | (d & 0xFFFFFF00u);
        int base = (p * 45 + k8) * 96 + lane;
        g_W4P[base]      = u0;
        g_W4P[base + 32] = u1;
        g_W4P[base + 64] = u2;
    }
    for (int i = idx; i < 21*25*32; i += stride) {
        int lane = i & 31;
        int k8 = (i >> 5) % 25;
        int q = (i >> 5) / 25;
        int lr = lane >> 2, lc = lane & 3;
        int col = q * 8 + lr;
        int row0 = k8 * 8 + lc, row1 = row0 + 4;
        float b0 = (col < 164) ? tf32r(Wp[row0 * 164 + col]) : 0.f;
        float b1 = (col < 164) ? tf32r(Wp[row1 * 164 + col]) : 0.f;
        int base = ((q * 25 + k8) * 32 + lane) * 2;
        g_WpM[base]     = b0;
        g_WpM[base + 1] = b1;
    }
    for (int i = idx; i < KRH * C_; i += stride) {
        int j = i / C_, cl = i - (i / C_) * C_;
        g_WcT[cl * KRH + j] = tf32r(Wc[i]);
    }
    for (int i = idx; i < IN_ * G4H; i += stride) g_Wxr[i] = tf32r(Wx[i]);
}

// ---------------- tf32 mma helper ----------------
__device__ __forceinline__ void mma_tf32(float& c0, float& c1, float& c2, float& c3,
                                         uint32_t a0, uint32_t a1, uint32_t a2, uint32_t a3,
                                         uint32_t b0, uint32_t b1) {
    asm volatile(
        "mma.sync.aligned.m16n8k8.row.col.f32.tf32.tf32.f32 "
        "{%0,%1,%2,%3}, {%4,%5,%6,%7}, {%8,%9}, {%0,%1,%2,%3};\n"
        : "+f"(c0), "+f"(c1), "+f"(c2), "+f"(c3)
        : "r"(a0), "r"(a1), "r"(a2), "r"(a3), "r"(b0), "r"(b1));
}

// ---------------- gemm0: Xpre = images @ Wx[:784] + b + offset row  (BM=128,BN=128) -------
#define NKT 25
#define G0_SMEM_FLOATS (2*128*36 + 2*32*132)    // 17664
__global__ __launch_bounds__(256) void gemm0_kernel(
    const float* __restrict__ A, const float* __restrict__ WxFull,
    const float* __restrict__ b_lstm, const int* __restrict__ labs,
    float* __restrict__ Cout)
{
    extern __shared__ float SG[];
    float* As = SG;            // [2][128][36]
    float* Bs = SG + 9216;     // [2][32][132]
    int tid = threadIdx.x, lane = tid & 31, warp = tid >> 5;
    int wm = warp >> 2, wn = warp & 3;
    int m0 = blockIdx.y * 128, n0 = blockIdx.x * 128;
    int lr = lane >> 2, lc = lane & 3;
    float c[4][4][4];
#pragma unroll
    for (int i = 0; i < 4; i++)
#pragma unroll
        for (int j = 0; j < 4; j++)
#pragma unroll
            for (int q = 0; q < 4; q++) c[i][j][q] = 0.f;

#define G0_ISSUE(IT) do {                                                       \
    int st_ = (IT) & 1;                                                         \
    int k0_ = (IT) * 32;                                                        \
    _Pragma("unroll")                                                           \
    for (int i_ = 0; i_ < 4; i_++) {                                            \
        int e_ = tid + i_ * 256;                                                \
        int row_ = e_ >> 3, c4_ = (e_ & 7) * 4;                                 \
        uint32_t sz_ = (k0_ + c4_ + 3 < IN_) ? 16u : 0u;                        \
        const float* src_ = A + (size_t)(m0 + row_) * IN_ + (sz_ ? (k0_ + c4_) : 0); \
        uint32_t da_ = (uint32_t)__cvta_generic_to_shared(&As[st_*4608 + row_*36 + c4_]); \
        asm volatile("cp.async.ca.shared.global [%0], [%1], 16, %2;" :: "r"(da_), "l"(src_), "r"(sz_)); \
    }                                                                           \
    _Pragma("unroll")                                                           \
    for (int i_ = 0; i_ < 4; i_++) {                                            \
        int e_ = tid + i_ * 256;                                                \
        int row_ = e_ >> 5, c4_ = (e_ & 31) * 4;                                \
        int krow_ = k0_ + row_;                                                 \
        int col_ = n0 + c4_;                                                    \
        uint32_t sz_ = (krow_ < IN_ && col_ + 3 < G4H) ? 16u : 0u;              \
        const float* src_ = g_Wxr + (sz_ ? ((size_t)krow_ * G4H + col_) : 0);   \
        uint32_t da_ = (uint32_t)__cvta_generic_to_shared(&Bs[st_*4224 + row_*132 + c4_]); \
        asm volatile("cp.async.ca.shared.global [%0], [%1], 16, %2;" :: "r"(da_), "l"(src_), "r"(sz_)); \
    }                                                                           \
    asm volatile("cp.async.commit_group;");                                     \
} while (0)

    G0_ISSUE(0);
    for (int it = 0; it < NKT; it++) {
        if (it + 1 < NKT) {
            G0_ISSUE(it + 1);
            asm volatile("cp.async.wait_group 1;");
        } else {
            asm volatile("cp.async.wait_group 0;");
        }
        __syncthreads();
        int st = it & 1;
        const float* Ast = As + st * 4608;
        const float* Bst = Bs + st * 4224;
#pragma unroll
        for (int k8 = 0; k8 < 4; k8++) {
            int kk = k8 * 8;
            uint32_t a[4][4];
#pragma unroll
            for (int mt = 0; mt < 4; mt++) {
                int arow = wm * 64 + mt * 16 + lr;
                a[mt][0] = __float_as_uint(tf32r(Ast[arow*36 + kk + lc]));
                a[mt][1] = __float_as_uint(tf32r(Ast[(arow + 8)*36 + kk + lc]));
                a[mt][2] = __float_as_uint(tf32r(Ast[arow*36 + kk + lc + 4]));
                a[mt][3] = __float_as_uint(tf32r(Ast[(arow + 8)*36 + kk + lc + 4]));
            }
#pragma unroll
            for (int nt = 0; nt < 4; nt++) {
                int bcol = wn * 32 + nt * 8 + lr;
                uint32_t b0 = __float_as_uint(Bst[(kk + lc)*132 + bcol]);
                uint32_t b1 = __float_as_uint(Bst[(kk + lc + 4)*132 + bcol]);
#pragma unroll
                for (int mt = 0; mt < 4; mt++)
                    mma_tf32(c[mt][nt][0], c[mt][nt][1], c[mt][nt][2], c[mt][nt][3],
                             a[mt][0], a[mt][1], a[mt][2], a[mt][3], b0, b1);
            }
        }
        __syncthreads();
    }

#pragma unroll
    for (int mt = 0; mt < 4; mt++) {
        int row0 = m0 + wm * 64 + mt * 16 + lr;
#pragma unroll
        for (int rr = 0; rr < 2; rr++) {
            int row = row0 + rr * 8;
            int tt = row % T_;
            int lab = (tt > 0) ? labs[row - 1] : 0;
#pragma unroll
            for (int nt = 0; nt < 4; nt++) {
                int col = n0 + wn * 32 + nt * 8 + 2 * lc;
#pragma unroll
                for (int cc = 0; cc < 2; cc++) {
                    int cg = col + cc;
                    if (cg < G4H) {
                        float v = c[mt][nt][rr * 2 + cc];
                        v += b_lstm[cg];
                        if (tt > 0) v += tf32r(WxFull[(size_t)(IN_ + lab) * G4H + cg]);
                        Cout[(size_t)row * G4H + cg] = v;
                    }
                }
            }
        }
    }
}

// ---------------- fused persistent recurrence kernel (R13 base; J -> mma) ----------------
#define OFF_SM   0                      // GB*5248 = 41984
#define OFF_RHT  41984                  // GB*361 = 2888 -> 44872
#define OFF_GU   44872                  // 6400 gates; union: SWR+MN+SKN
#define OFF_SWR  (OFF_GU)               // 4096
#define OFF_MN   (OFF_GU + 4096)        // 1024
#define OFF_SKN  (OFF_GU + 5120)        // 1280
#define OFF_WRO  51272                  // 4096 -> 55368
#define OFF_WU   55368                  // 1024 -> 56392
#define OFF_SKT  56392                  // 1280 -> 57672
#define OFF_KN   57672                  // 32
#define OFF_SSIG 57704                  // 32
#define OFF_SLOG 57736                  // 40
#define OFF_LU   57776                  // 32 ints
#define SMEM_FLOATS 57808
#define SMEM_BYTES  (SMEM_FLOATS * 4)   // 231232 <= 232448

__global__ __launch_bounds__(TPB, 1) void fused_kernel(
    const float* __restrict__ bp, const float* __restrict__ bc,
    const int* __restrict__ labels, float* __restrict__ out)
{
    extern __shared__ float S[];
    int tid = threadIdx.x;
    int lane = tid & 31, warp = tid >> 5;
    int bb = blockIdx.x * GB;
    int* s_luI = (int*)(S + OFF_LU);
    const int lr = lane >> 2, lc = lane & 3;

    float c_reg[4] = {0.f, 0.f, 0.f, 0.f};

    // ---- state init ----
    for (int i = tid; i < GB * NSLOT * MSTR; i += TPB) S[OFF_SM + i] = 1e-6f;
    for (int i = tid; i < GB * 361; i += TPB) {
        int j = i % 361;
        S[OFF_RHT + i] = (j < R_*D_) ? tf32r(1e-6f) : 0.f;
    }
    for (int i = tid; i < GB * NSLOT; i += TPB) S[OFF_WU + i] = ((i & 127) == 0) ? 1.f : 0.f;
    for (int i = tid; i < GB * 512; i += TPB)   S[OFF_WRO + i] = ((i & 127) == 0) ? 1.f : 0.f;
    __syncthreads();

    for (int t = 0; t < T_; t++) {
        // ---- A: gates GEMM [8x360]@[360x800] via mma + 24-bit packed W, + Xpre epilogue ----
        {
            const float* rhRow = S + OFF_RHT + lr * 361;
            for (int p = warp; p < 50; p += NW) {
                float c00 = 0.f, c01 = 0.f, c02 = 0.f, c03 = 0.f;
                float c10 = 0.f, c11 = 0.f, c12 = 0.f, c13 = 0.f;
                const uint32_t* wp = g_W4P + p * (45 * 96) + lane;
#pragma unroll 5
                for (int k8 = 0; k8 < 45; k8++) {
                    uint32_t u0 = wp[0], u1 = wp[32], u2 = wp[64];
                    wp += 96;
                    uint32_t wx = u0 << 8;
                    uint32_t wy = ((u0 >> 24) << 8) | (u1 << 16);
                    uint32_t wz = ((u1 >> 16) << 8) | (u2 << 24);
                    uint32_t ww = u2 & 0xFFFFFF00u;
                    uint32_t a0 = __float_as_uint(rhRow[k8 * 8 + lc]);
                    uint32_t a2 = __float_as_uint(rhRow[k8 * 8 + 4 + lc]);
                    mma_tf32(c00, c01, c02, c03, a0, 0u, a2, 0u, wx, wy);
                    mma_tf32(c10, c11, c12, c13, a0, 0u, a2, 0u, wz, ww);
                }
                int col0 = p * 16 + 2 * lc;
                const float* xp = g_Xpre + ((size_t)(bb + lr) * T_ + t) * G4H;
                float* gr = S + OFF_GU + lr * 800;
                gr[col0]     = c00 + xp[col0];
                gr[col0 + 1] = c01 + xp[col0 + 1];
                gr[col0 + 8] = c10 + xp[col0 + 8];
                gr[col0 + 9] = c11 + xp[col0 + 9];
            }
        }
        __syncthreads();

        // ---- B: LSTM pointwise ----
#pragma unroll
        for (int s = 0; s < 4; s++) {
            int i = tid + s * TPB;
            if (i < GB * H_) {
                int g = i / H_, u = i - g * H_;
                const float* gg = S + OFF_GU + g * 800;
                float ig = gg[u], fg = gg[200 + u], gz = gg[400 + u], og = gg[600 + u];
                float c_new = sigm(fg) * c_reg[s] + sigm(ig) * tanh_acc(gz);
                c_reg[s] = c_new;
                float h = sigm(og) * tanh_acc(c_new);
                S[OFF_RHT + g * 361 + R_*D_ + u] = tf32r(h);
            }
        }
        __syncthreads();

        // ---- C: keys via mma [8x200]@[200x164] + M row norms ----
        {
            const float* hRow = S + OFF_RHT + lr * 361 + R_*D_;
            for (int q = warp; q < 21; q += NW) {
                float k0v = 0.f, k1v = 0.f, k2d = 0.f, k3d = 0.f;
                const float2* wp2 = reinterpret_cast<const float2*>(g_WpM) + (q * 25) * 32 + lane;
#pragma unroll 5
                for (int k8 = 0; k8 < 25; k8++) {
                    float2 b = wp2[k8 * 32];
                    uint32_t a0 = __float_as_uint(hRow[k8 * 8 + lc]);
                    uint32_t a2 = __float_as_uint(hRow[k8 * 8 + 4 + lc]);
                    mma_tf32(k0v, k1v, k2d, k3d, a0, 0u, a2, 0u,
                             __float_as_uint(b.x), __float_as_uint(b.y));
                }
                int g = lr;
#pragma unroll
                for (int cc = 0; cc < 2; cc++) {
                    int j = q * 8 + 2 * lc + cc;
                    if (j < 164) {
                        float acc = (cc ? k1v : k0v) + bp[j];
                        int r = j / 41, w = j - r * 41;
                        if (w < D_) S[OFF_SKT + g * 160 + r * 40 + w] = tanh_acc(acc);
                        else        S[OFF_SSIG + g * 4 + r] = sigm(acc);
                    }
                }
            }
        }
#pragma unroll
        for (int s = 0; s < 2; s++) {
            int p = tid + s * TPB;
            int g = p >> 7, n = p & 127;
            const float* Mr = S + OFF_SM + g * NSLOT * MSTR + n * MSTR;
            float ss = 0.f;
            for (int d = 0; d < D_; d++) ss = fmaf(Mr[d], Mr[d], ss);
            S[OFF_MN + p] = __fsqrt_rn(ss) + 1e-8f;
        }
        __syncthreads();

        // ---- D: key norms (tid<32) + LU selection (warps 8..15) ----
        if (tid < 32) {
            int g = tid >> 2, r = tid & 3;
            const float* kk = S + OFF_SKT + g * 160 + r * 40;
            float ss = 0.f;
            for (int d = 0; d < D_; d++) ss = fmaf(kk[d], kk[d], ss);
            S[OFF_KN + tid] = __fsqrt_rn(ss) + 1e-8f;
        } else if (warp >= 8 && warp < 16) {
            int g = warp - 8;
            const float* wu = S + OFF_WU + g * NSLOT;
            float v0 = wu[lane], v1 = wu[lane + 32], v2 = wu[lane + 64], v3 = wu[lane + 96];
            int i0 = lane, i1 = lane + 32, i2 = lane + 64, i3 = lane + 96;
#pragma unroll
            for (int s = 0; s < R_; s++) {
                float bv = v0; int bi = i0;
                if (v1 < bv || (v1 == bv && i1 < bi)) { bv = v1; bi = i1; }
                if (v2 < bv || (v2 == bv && i2 < bi)) { bv = v2; bi = i2; }
                if (v3 < bv || (v3 == bv && i3 < bi)) { bv = v3; bi = i3; }
#pragma unroll
                for (int o = 16; o > 0; o >>= 1) {
                    float ov = __shfl_xor_sync(0xffffffffu, bv, o);
                    int   oi = __shfl_xor_sync(0xffffffffu, bi, o);
                    if (ov < bv || (ov == bv && oi < bi)) { bv = ov; bi = oi; }
                }
                if (lane == 0) s_luI[g * 4 + s] = bi;
                if      (bi == i0) v0 = 3.0e38f;
                else if (bi == i1) v1 = 3.0e38f;
                else if (bi == i2) v2 = 3.0e38f;
                else if (bi == i3) v3 = 3.0e38f;
            }
        }
        __syncthreads();

        // ---- E: round keys; build skn ----
#pragma unroll
        for (int s = 0; s < 3; s++) {
            int i = tid + s * TPB;
            if (i < GB * 160) {
                int g = i / 160, j = i - g * 160;
                int r = j / 40;
                float raw = S[OFF_SKT + i];
                float nrm = S[OFF_KN + g * 4 + r];
                S[OFF_SKN + i] = tf32r(__fdiv_rn(raw, nrm));
                S[OFF_SKT + i] = tf32r(raw);
            }
        }
        __syncthreads();

        // ---- F: cosine logits ----
#pragma unroll
        for (int s = 0; s < 2; s++) {
            int p = tid + s * TPB;
            int g = p >> 7, n = p & 127;
            const float* Mr = S + OFF_SM + g * NSLOT * MSTR + n * MSTR;
            const float* kn = S + OFF_SKN + g * 160;
            float rinv = __fdiv_rn(1.f, S[OFF_MN + p]);
            float a0 = 0.f, a1 = 0.f, a2 = 0.f, a3 = 0.f;
            for (int d = 0; d < D_; d++) {
                float mn = tf32r(Mr[d] * rinv);
                a0 = fmaf(mn, kn[d],       a0);
                a1 = fmaf(mn, kn[40 + d],  a1);
                a2 = fmaf(mn, kn[80 + d],  a2);
                a3 = fmaf(mn, kn[120 + d], a3);
            }
            float* sw = S + OFF_SWR + g * 512;
            sw[n] = a0; sw[128 + n] = a1; sw[256 + n] = a2; sw[384 + n] = a3;
        }
        __syncthreads();

        // ---- G: softmax per (g,r) ----
        for (int row = warp; row < GB * R_; row += NW) {
            int g = row >> 2, r = row & 3;
            float* sw = S + OFF_SWR + g * 512 + r * 128;
            float v0 = sw[lane], v1 = sw[lane + 32], v2 = sw[lane + 64], v3 = sw[lane + 96];
            float mx = fmaxf(fmaxf(v0, v1), fmaxf(v2, v3));
            for (int o = 16; o > 0; o >>= 1) mx = fmaxf(mx, __shfl_xor_sync(0xffffffffu, mx, o));
            float e0 = exp_acc(v0 - mx), e1 = exp_acc(v1 - mx), e2 = exp_acc(v2 - mx), e3 = exp_acc(v3 - mx);
            float ssum = e0 + e1 + e2 + e3;
            for (int o = 16; o > 0; o >>= 1) ssum += __shfl_xor_sync(0xffffffffu, ssum, o);
            sw[lane]      = __fdiv_rn(e0, ssum);
            sw[lane + 32] = __fdiv_rn(e1, ssum);
            sw[lane + 64] = __fdiv_rn(e2, ssum);
            sw[lane + 96] = __fdiv_rn(e3, ssum);
        }
        __syncthreads();

        // ---- H: usage update + wrOld<-swr + memory write + round swr in place ----
#pragma unroll
        for (int s = 0; s < 2; s++) {
            int p = tid + s * TPB;
            int g = p >> 7, n = p & 127;
            float* wro = S + OFF_WRO + g * 512;
            float* sw  = S + OFF_SWR + g * 512;
            int lu0 = s_luI[g*4], lu1 = s_luI[g*4+1], lu2 = s_luI[g*4+2], lu3 = s_luI[g*4+3];
            float wlu = (n == lu0 || n == lu1 || n == lu2 || n == lu3) ? 1.f : 0.f;
            float sg0 = S[OFF_SSIG + g*4], sg1 = S[OFF_SSIG + g*4+1];
            float sg2 = S[OFF_SSIG + g*4+2], sg3 = S[OFF_SSIG + g*4+3];
            float wo0 = wro[n], wo1 = wro[128+n], wo2 = wro[256+n], wo3 = wro[384+n];
            float ww0 = sg0 * wo0 + (1.f - sg0) * wlu;
            float ww1 = sg1 * wo1 + (1.f - sg1) * wlu;
            float ww2 = sg2 * wo2 + (1.f - sg2) * wlu;
            float ww3 = sg3 * wo3 + (1.f - sg3) * wlu;
            float sr0 = sw[n], sr1 = sw[128+n], sr2 = sw[256+n], sr3 = sw[384+n];
            float v = 0.95f * S[OFF_WU + p];
            v += sr0 + ww0; v += sr1 + ww1; v += sr2 + ww2; v += sr3 + ww3;
            S[OFF_WU + p] = v;
            wro[n] = sr0; wro[128+n] = sr1; wro[256+n] = sr2; wro[384+n] = sr3;
            sw[n] = tf32r(sr0); sw[128+n] = tf32r(sr1); sw[256+n] = tf32r(sr2); sw[384+n] = tf32r(sr3);
            float wt0 = tf32r(ww0), wt1 = tf32r(ww1), wt2 = tf32r(ww2), wt3 = tf32r(ww3);
            float* Mr = S + OFF_SM + g * NSLOT * MSTR + n * MSTR;
            const float* kT = S + OFF_SKT + g * 160;
            bool zero_base = (n == lu3);
            for (int d = 0; d < D_; d++) {
                float base = zero_base ? 0.f : Mr[d];
                float add = 0.f;
                add = fmaf(wt0, kT[d],       add);
                add = fmaf(wt1, kT[40 + d],  add);
                add = fmaf(wt2, kT[80 + d],  add);
                add = fmaf(wt3, kT[120 + d], add);
                Mr[d] = base + add;
            }
        }
        __syncthreads();

        // ---- J: read einsum via mma — warp g (<8) computes r_new[g] = swr[g] @ M[g] ----
        if (warp < GB) {
            int g = warp;
            const float* swB = S + OFF_SWR + g * 512;          // rounded read weights
            const float* Mg  = S + OFF_SM + g * NSLOT * MSTR;  // raw M, round per load
            float cJ[5][4];
#pragma unroll
            for (int nt = 0; nt < 5; nt++) {
                cJ[nt][0] = 0.f; cJ[nt][1] = 0.f; cJ[nt][2] = 0.f; cJ[nt][3] = 0.f;
            }
#pragma unroll
            for (int k8 = 0; k8 < 16; k8++) {
                int kk = k8 * 8;
                uint32_t a0 = 0u, a2 = 0u;
                if (lr < 4) {   // A rows 0..3 = read-weight rows; rows 4..15 zero
                    a0 = __float_as_uint(swB[lr * 128 + kk + lc]);
                    a2 = __float_as_uint(swB[lr * 128 + kk + lc + 4]);
                }
#pragma unroll
                for (int nt = 0; nt < 5; nt++) {
                    int d0 = nt * 8 + lr;
                    uint32_t b0 = __float_as_uint(tf32r(Mg[(kk + lc) * MSTR + d0]));
                    uint32_t b1 = __float_as_uint(tf32r(Mg[(kk + lc + 4) * MSTR + d0]));
                    mma_tf32(cJ[nt][0], cJ[nt][1], cJ[nt][2], cJ[nt][3],
                             a0, 0u, a2, 0u, b0, b1);
                }
            }
            if (lr < 4) {
#pragma unroll
                for (int nt = 0; nt < 5; nt++) {
                    int d = nt * 8 + 2 * lc;
                    S[OFF_RHT + g * 361 + lr * 40 + d]     = tf32r(cJ[nt][0]);
                    S[OFF_RHT + g * 361 + lr * 40 + d + 1] = tf32r(cJ[nt][1]);
                }
            }
        }
        __syncthreads();

        // ---- K: classifier (transposed Wc, coalesced) ----
        for (int o = warp; o < GB * C_; o += NW) {
            int g = o / C_, cl = o - g * C_;
            const float* rh = S + OFF_RHT + g * 361;
            const float* wc = g_WcT + cl * KRH;
            float acc = 0.f;
            for (int j = lane; j < KRH; j += 32) {
                float v = (j < H_) ? rh[R_*D_ + j] : rh[j - H_];
                acc = fmaf(v, wc[j], acc);
            }
#pragma unroll
            for (int o2 = 16; o2 > 0; o2 >>= 1) acc += __shfl_xor_sync(0xffffffffu, acc, o2);
            if (lane == 0) S[OFF_SLOG + o] = acc + bc[cl];
        }
        __syncthreads();

        // ---- L: probs + loss/acc rows ----
        if (tid < GB) {
            int g = tid;
            int m = (bb + g) * T_ + t;
            const float* lg = S + OFF_SLOG + g * C_;
            float mx = lg[0]; int am = 0;
            for (int c = 1; c < C_; c++) if (lg[c] > mx) { mx = lg[c]; am = c; }
            float e[C_], ssum = 0.f;
            for (int c = 0; c < C_; c++) { e[c] = exp_acc(lg[c] - mx); ssum += e[c]; }
            float pr[C_];
            for (int c = 0; c < C_; c++) { pr[c] = __fdiv_rn(e[c], ssum); out[m * C_ + c] = pr[c]; }
            float mp = pr[0];
            for (int c = 1; c < C_; c++) mp = fmaxf(mp, pr[c]);
            float se = 0.f;
            for (int c = 0; c < C_; c++) se += exp_acc(pr[c] - mp);
            int lab = labels[m];
            g_rowloss[m] = (float)(log((double)se)) + mp - pr[lab];
            g_rowcorr[m] = (am == lab) ? 1.f : 0.f;
        }
        __syncthreads();
    }
}

// ---------------- deterministic final reduction ----------------
__global__ __launch_bounds__(1024) void finalize_kernel(float* __restrict__ out) {
    __shared__ float sl[1024], sa[1024];
    int tid = threadIdx.x;
    float l = 0.f, a = 0.f;
    for (int i = tid; i < BT; i += 1024) { l += g_rowloss[i]; a += g_rowcorr[i]; }
    sl[tid] = l; sa[tid] = a;
    __syncthreads();
    for (int s = 512; s > 0; s >>= 1) {
        if (tid < s) { sl[tid] += sl[tid + s]; sa[tid] += sa[tid + s]; }
        __syncthreads();
    }
    if (tid == 0) {
        out[BT * C_]     = __fdiv_rn(sl[0], (float)BT);
        out[BT * C_ + 1] = __fdiv_rn(sa[0], (float)BT);
    }
}

// ---------------- launch ----------------
extern "C" void kernel_launch(void* const* d_in, const int* in_sizes, int n_in,
                              void* d_out, int out_size) {
    const float* images = (const float*)d_in[0];
    const int*   labels = (const int*)d_in[1];
    const float* Wx     = (const float*)d_in[2];
    const float* Wh     = (const float*)d_in[3];
    const float* b_lstm = (const float*)d_in[4];
    const float* Wp     = (const float*)d_in[5];
    const float* bp     = (const float*)d_in[6];
    const float* Wc     = (const float*)d_in[7];
    const float* bc     = (const float*)d_in[8];
    float* out = (float*)d_out;

    float* pXpre;
    cudaGetSymbolAddress((void**)&pXpre, g_Xpre);

    cudaFuncSetAttribute(fused_kernel, cudaFuncAttributeMaxDynamicSharedMemorySize, SMEM_BYTES);
    cudaFuncSetAttribute(gemm0_kernel, cudaFuncAttributeMaxDynamicSharedMemorySize, G0_SMEM_FLOATS * 4);

    init_kernel<<<320, 256>>>(Wx, Wh, Wp, Wc);

    {
        dim3 grid(7, BT / 128);
        gemm0_kernel<<<grid, 256, G0_SMEM_FLOATS * 4>>>(images, Wx, b_lstm, labels, pXpre);
    }

    fused_kernel<<<NBLK, TPB, SMEM_BYTES>>>(bp, bc, labels, out);

    finalize_kernel<<<1, 1024>>>(out);
}

// round 17
// speedup vs baseline: 1.1126x; 1.0010x over previous
#include <cuda_runtime.h>
#include <math.h>
#include <stdint.h>

#define B_   1024
#define T_   50
#define IN_  784
#define NSLOT 128
#define D_   40
#define H_   200
#define R_   4
#define C_   5
#define G4H  800
#define KRH  360
#define BT   (B_*T_)
#define GB   8            // batches per block
#define NBLK (B_/GB)      // 128
#define TPB  512
#define NW   (TPB/32)     // 16 warps
#define MSTR 41           // padded M row stride (conflict-free)

// ---------------- device globals ----------------
__device__ float g_Xpre[BT * G4H];                   // images@Wx + b + offset row (fp32)
__device__ __align__(16) uint32_t g_W4P[50*45*96];   // 24-bit packed tf32 Wrh (lossless)
__device__ __align__(16) float g_WpM[21*25*64];      // mma-fragment tf32 Wp (float2/lane)
__device__ float g_WcT[C_ * KRH];                    // tf32-rounded Wc, TRANSPOSED [C][KRH]
__device__ __align__(16) float g_Wxr[IN_ * G4H];     // tf32-rounded Wx rows [0,784)
__device__ float g_rowloss[BT];
__device__ float g_rowcorr[BT];

__device__ __forceinline__ float tf32r(float x) {
    float y;
    asm("cvt.rna.tf32.f32 %0, %1;" : "=f"(y) : "f"(x));
    return y;
}

// ---------------- precise transcendentals (fast-math immune) ----------------
__device__ __forceinline__ float exp_acc(float x) {
    x = fminf(fmaxf(x, -87.0f), 88.0f);
    float n = rintf(x * 1.44269504088896341f);
    float r = fmaf(n, -0.693359375f, x);
    r = fmaf(n, 2.12194440e-4f, r);
    float z = r * r;
    float p = 1.9875691500e-4f;
    p = fmaf(p, r, 1.3981999507e-3f);
    p = fmaf(p, r, 8.3334519073e-3f);
    p = fmaf(p, r, 4.1665795894e-2f);
    p = fmaf(p, r, 1.6666665459e-1f);
    p = fmaf(p, r, 5.0000001201e-1f);
    float res = fmaf(p, z, r) + 1.0f;
    int i = (int)n;
    float scale = __int_as_float((i + 127) << 23);
    return res * scale;
}
__device__ __forceinline__ float expm1_small(float y) {
    float p = 2.7557319e-7f;
    p = fmaf(p, y, 2.4801587e-5f);
    p = fmaf(p, y, 1.9841270e-4f);
    p = fmaf(p, y, 1.3888889e-3f);
    p = fmaf(p, y, 8.3333333e-3f);
    p = fmaf(p, y, 4.1666667e-2f);
    p = fmaf(p, y, 1.6666667e-1f);
    p = fmaf(p, y, 0.5f);
    p = fmaf(p, y, 1.0f);
    return y * p;
}
__device__ __forceinline__ float tanh_acc(float x) {
    float a = fabsf(x);
    float t;
    if (a < 0.51f) {
        float em1 = expm1_small(2.0f * a);
        t = __fdiv_rn(em1, em1 + 2.0f);
    } else if (a < 9.1f) {
        float e = exp_acc(2.0f * a);
        t = 1.0f - __fdiv_rn(2.0f, e + 1.0f);
    } else {
        t = 1.0f;
    }
    return copysignf(t, x);
}
__device__ __forceinline__ float sigm(float x) {
    float e = exp_acc(-x);
    return __fdiv_rn(1.0f, 1.0f + e);
}

// ---------------- init: build packed / pre-rounded weights ----------------
__global__ void init_kernel(const float* __restrict__ Wx, const float* __restrict__ Wh,
                            const float* __restrict__ Wp, const float* __restrict__ Wc) {
    int idx = blockIdx.x * blockDim.x + threadIdx.x;
    int stride = gridDim.x * blockDim.x;
    for (int i = idx; i < 50*45*32; i += stride) {
        int lane = i & 31;
        int k8 = (i >> 5) % 45;
        int p = (i >> 5) / 45;
        int lr = lane >> 2, lc = lane & 3;
        uint32_t vb[4];
#pragma unroll
        for (int q = 0; q < 4; q++) {
            int row = k8 * 8 + (q & 1) * 4 + lc;
            int col = p * 16 + (q >> 1) * 8 + lr;
            float v = (row < R_*D_) ? Wx[(size_t)(IN_ + C_ + row) * G4H + col]
                                    : Wh[(size_t)(row - R_*D_) * G4H + col];
            vb[q] = __float_as_uint(tf32r(v));
        }
        uint32_t a = vb[0], b = vb[1], c = vb[2], d = vb[3];
        uint32_t u0 = (a >> 8) | (b << 16);
        uint32_t u1 = (b >> 16) | ((c >> 8) << 16);
        uint32_t u2 = (c >> 24) | (d & 0xFFFFFF00u);
        int base = (p * 45 + k8) * 96 + lane;
        g_W4P[base]      = u0;
        g_W4P[base + 32] = u1;
        g_W4P[base + 64] = u2;
    }
    for (int i = idx; i < 21*25*32; i += stride) {
        int lane = i & 31;
        int k8 = (i >> 5) % 25;
        int q = (i >> 5) / 25;
        int lr = lane >> 2, lc = lane & 3;
        int col = q * 8 + lr;
        int row0 = k8 * 8 + lc, row1 = row0 + 4;
        float b0 = (col < 164) ? tf32r(Wp[row0 * 164 + col]) : 0.f;
        float b1 = (col < 164) ? tf32r(Wp[row1 * 164 + col]) : 0.f;
        int base = ((q * 25 + k8) * 32 + lane) * 2;
        g_WpM[base]     = b0;
        g_WpM[base + 1] = b1;
    }
    for (int i = idx; i < KRH * C_; i += stride) {
        int j = i / C_, cl = i - (i / C_) * C_;
        g_WcT[cl * KRH + j] = tf32r(Wc[i]);
    }
    for (int i = idx; i < IN_ * G4H; i += stride) g_Wxr[i] = tf32r(Wx[i]);
}

// ---------------- tf32 mma helper ----------------
__device__ __forceinline__ void mma_tf32(float& c0, float& c1, float& c2, float& c3,
                                         uint32_t a0, uint32_t a1, uint32_t a2, uint32_t a3,
                                         uint32_t b0, uint32_t b1) {
    asm volatile(
        "mma.sync.aligned.m16n8k8.row.col.f32.tf32.tf32.f32 "
        "{%0,%1,%2,%3}, {%4,%5,%6,%7}, {%8,%9}, {%0,%1,%2,%3};\n"
        : "+f"(c0), "+f"(c1), "+f"(c2), "+f"(c3)
        : "r"(a0), "r"(a1), "r"(a2), "r"(a3), "r"(b0), "r"(b1));
}

// ---------------- gemm0: Xpre = images @ Wx[:784] + b + offset row  (BM=128,BN=128) -------
#define NKT 25
#define G0_SMEM_FLOATS (2*128*36 + 2*32*132)    // 17664
__global__ __launch_bounds__(256) void gemm0_kernel(
    const float* __restrict__ A, const float* __restrict__ WxFull,
    const float* __restrict__ b_lstm, const int* __restrict__ labs,
    float* __restrict__ Cout)
{
    extern __shared__ float SG[];
    float* As = SG;            // [2][128][36]
    float* Bs = SG + 9216;     // [2][32][132]
    int tid = threadIdx.x, lane = tid & 31, warp = tid >> 5;
    int wm = warp >> 2, wn = warp & 3;
    int m0 = blockIdx.y * 128, n0 = blockIdx.x * 128;
    int lr = lane >> 2, lc = lane & 3;
    float c[4][4][4];
#pragma unroll
    for (int i = 0; i < 4; i++)
#pragma unroll
        for (int j = 0; j < 4; j++)
#pragma unroll
            for (int q = 0; q < 4; q++) c[i][j][q] = 0.f;

#define G0_ISSUE(IT) do {                                                       \
    int st_ = (IT) & 1;                                                         \
    int k0_ = (IT) * 32;                                                        \
    _Pragma("unroll")                                                           \
    for (int i_ = 0; i_ < 4; i_++) {                                            \
        int e_ = tid + i_ * 256;                                                \
        int row_ = e_ >> 3, c4_ = (e_ & 7) * 4;                                 \
        uint32_t sz_ = (k0_ + c4_ + 3 < IN_) ? 16u : 0u;                        \
        const float* src_ = A + (size_t)(m0 + row_) * IN_ + (sz_ ? (k0_ + c4_) : 0); \
        uint32_t da_ = (uint32_t)__cvta_generic_to_shared(&As[st_*4608 + row_*36 + c4_]); \
        asm volatile("cp.async.ca.shared.global [%0], [%1], 16, %2;" :: "r"(da_), "l"(src_), "r"(sz_)); \
    }                                                                           \
    _Pragma("unroll")                                                           \
    for (int i_ = 0; i_ < 4; i_++) {                                            \
        int e_ = tid + i_ * 256;                                                \
        int row_ = e_ >> 5, c4_ = (e_ & 31) * 4;                                \
        int krow_ = k0_ + row_;                                                 \
        int col_ = n0 + c4_;                                                    \
        uint32_t sz_ = (krow_ < IN_ && col_ + 3 < G4H) ? 16u : 0u;              \
        const float* src_ = g_Wxr + (sz_ ? ((size_t)krow_ * G4H + col_) : 0);   \
        uint32_t da_ = (uint32_t)__cvta_generic_to_shared(&Bs[st_*4224 + row_*132 + c4_]); \
        asm volatile("cp.async.ca.shared.global [%0], [%1], 16, %2;" :: "r"(da_), "l"(src_), "r"(sz_)); \
    }                                                                           \
    asm volatile("cp.async.commit_group;");                                     \
} while (0)

    G0_ISSUE(0);
    for (int it = 0; it < NKT; it++) {
        if (it + 1 < NKT) {
            G0_ISSUE(it + 1);
            asm volatile("cp.async.wait_group 1;");
        } else {
            asm volatile("cp.async.wait_group 0;");
        }
        __syncthreads();
        int st = it & 1;
        const float* Ast = As + st * 4608;
        const float* Bst = Bs + st * 4224;
#pragma unroll
        for (int k8 = 0; k8 < 4; k8++) {
            int kk = k8 * 8;
            uint32_t a[4][4];
#pragma unroll
            for (int mt = 0; mt < 4; mt++) {
                int arow = wm * 64 + mt * 16 + lr;
                a[mt][0] = __float_as_uint(tf32r(Ast[arow*36 + kk + lc]));
                a[mt][1] = __float_as_uint(tf32r(Ast[(arow + 8)*36 + kk + lc]));
                a[mt][2] = __float_as_uint(tf32r(Ast[arow*36 + kk + lc + 4]));
                a[mt][3] = __float_as_uint(tf32r(Ast[(arow + 8)*36 + kk + lc + 4]));
            }
#pragma unroll
            for (int nt = 0; nt < 4; nt++) {
                int bcol = wn * 32 + nt * 8 + lr;
                uint32_t b0 = __float_as_uint(Bst[(kk + lc)*132 + bcol]);
                uint32_t b1 = __float_as_uint(Bst[(kk + lc + 4)*132 + bcol]);
#pragma unroll
                for (int mt = 0; mt < 4; mt++)
                    mma_tf32(c[mt][nt][0], c[mt][nt][1], c[mt][nt][2], c[mt][nt][3],
                             a[mt][0], a[mt][1], a[mt][2], a[mt][3], b0, b1);
            }
        }
        __syncthreads();
    }

#pragma unroll
    for (int mt = 0; mt < 4; mt++) {
        int row0 = m0 + wm * 64 + mt * 16 + lr;
#pragma unroll
        for (int rr = 0; rr < 2; rr++) {
            int row = row0 + rr * 8;
            int tt = row % T_;
            int lab = (tt > 0) ? labs[row - 1] : 0;
#pragma unroll
            for (int nt = 0; nt < 4; nt++) {
                int col = n0 + wn * 32 + nt * 8 + 2 * lc;
#pragma unroll
                for (int cc = 0; cc < 2; cc++) {
                    int cg = col + cc;
                    if (cg < G4H) {
                        float v = c[mt][nt][rr * 2 + cc];
                        v += b_lstm[cg];
                        if (tt > 0) v += tf32r(WxFull[(size_t)(IN_ + lab) * G4H + cg]);
                        Cout[(size_t)row * G4H + cg] = v;
                    }
                }
            }
        }
    }
}

// ---------------- fused persistent recurrence kernel (R16 base; F -> mma) ----------------
#define OFF_SM   0                      // GB*5248 = 41984
#define OFF_RHT  41984                  // GB*361 = 2888 -> 44872
#define OFF_GU   44872                  // 6400 gates; union: SWR+MN+SKN
#define OFF_SWR  (OFF_GU)               // 4096
#define OFF_MN   (OFF_GU + 4096)        // 1024 (now stores rinv)
#define OFF_SKN  (OFF_GU + 5120)        // 1280
#define OFF_WRO  51272                  // 4096 -> 55368
#define OFF_WU   55368                  // 1024 -> 56392
#define OFF_SKT  56392                  // 1280 -> 57672
#define OFF_KN   57672                  // 32
#define OFF_SSIG 57704                  // 32
#define OFF_SLOG 57736                  // 40
#define OFF_LU   57776                  // 32 ints
#define SMEM_FLOATS 57808
#define SMEM_BYTES  (SMEM_FLOATS * 4)   // 231232 <= 232448

__global__ __launch_bounds__(TPB, 1) void fused_kernel(
    const float* __restrict__ bp, const float* __restrict__ bc,
    const int* __restrict__ labels, float* __restrict__ out)
{
    extern __shared__ float S[];
    int tid = threadIdx.x;
    int lane = tid & 31, warp = tid >> 5;
    int bb = blockIdx.x * GB;
    int* s_luI = (int*)(S + OFF_LU);
    const int lr = lane >> 2, lc = lane & 3;

    float c_reg[4] = {0.f, 0.f, 0.f, 0.f};

    // ---- state init ----
    for (int i = tid; i < GB * NSLOT * MSTR; i += TPB) S[OFF_SM + i] = 1e-6f;
    for (int i = tid; i < GB * 361; i += TPB) {
        int j = i % 361;
        S[OFF_RHT + i] = (j < R_*D_) ? tf32r(1e-6f) : 0.f;
    }
    for (int i = tid; i < GB * NSLOT; i += TPB) S[OFF_WU + i] = ((i & 127) == 0) ? 1.f : 0.f;
    for (int i = tid; i < GB * 512; i += TPB)   S[OFF_WRO + i] = ((i & 127) == 0) ? 1.f : 0.f;
    __syncthreads();

    for (int t = 0; t < T_; t++) {
        // ---- A: gates GEMM [8x360]@[360x800] via mma + 24-bit packed W, + Xpre epilogue ----
        {
            const float* rhRow = S + OFF_RHT + lr * 361;
            for (int p = warp; p < 50; p += NW) {
                float c00 = 0.f, c01 = 0.f, c02 = 0.f, c03 = 0.f;
                float c10 = 0.f, c11 = 0.f, c12 = 0.f, c13 = 0.f;
                const uint32_t* wp = g_W4P + p * (45 * 96) + lane;
#pragma unroll 5
                for (int k8 = 0; k8 < 45; k8++) {
                    uint32_t u0 = wp[0], u1 = wp[32], u2 = wp[64];
                    wp += 96;
                    uint32_t wx = u0 << 8;
                    uint32_t wy = ((u0 >> 24) << 8) | (u1 << 16);
                    uint32_t wz = ((u1 >> 16) << 8) | (u2 << 24);
                    uint32_t ww = u2 & 0xFFFFFF00u;
                    uint32_t a0 = __float_as_uint(rhRow[k8 * 8 + lc]);
                    uint32_t a2 = __float_as_uint(rhRow[k8 * 8 + 4 + lc]);
                    mma_tf32(c00, c01, c02, c03, a0, 0u, a2, 0u, wx, wy);
                    mma_tf32(c10, c11, c12, c13, a0, 0u, a2, 0u, wz, ww);
                }
                int col0 = p * 16 + 2 * lc;
                const float* xp = g_Xpre + ((size_t)(bb + lr) * T_ + t) * G4H;
                float* gr = S + OFF_GU + lr * 800;
                gr[col0]     = c00 + xp[col0];
                gr[col0 + 1] = c01 + xp[col0 + 1];
                gr[col0 + 8] = c10 + xp[col0 + 8];
                gr[col0 + 9] = c11 + xp[col0 + 9];
            }
        }
        __syncthreads();

        // ---- B: LSTM pointwise ----
#pragma unroll
        for (int s = 0; s < 4; s++) {
            int i = tid + s * TPB;
            if (i < GB * H_) {
                int g = i / H_, u = i - g * H_;
                const float* gg = S + OFF_GU + g * 800;
                float ig = gg[u], fg = gg[200 + u], gz = gg[400 + u], og = gg[600 + u];
                float c_new = sigm(fg) * c_reg[s] + sigm(ig) * tanh_acc(gz);
                c_reg[s] = c_new;
                float h = sigm(og) * tanh_acc(c_new);
                S[OFF_RHT + g * 361 + R_*D_ + u] = tf32r(h);
            }
        }
        __syncthreads();

        // ---- C: keys via mma [8x200]@[200x164] + M row rinv ----
        {
            const float* hRow = S + OFF_RHT + lr * 361 + R_*D_;
            for (int q = warp; q < 21; q += NW) {
                float k0v = 0.f, k1v = 0.f, k2d = 0.f, k3d = 0.f;
                const float2* wp2 = reinterpret_cast<const float2*>(g_WpM) + (q * 25) * 32 + lane;
#pragma unroll 5
                for (int k8 = 0; k8 < 25; k8++) {
                    float2 b = wp2[k8 * 32];
                    uint32_t a0 = __float_as_uint(hRow[k8 * 8 + lc]);
                    uint32_t a2 = __float_as_uint(hRow[k8 * 8 + 4 + lc]);
                    mma_tf32(k0v, k1v, k2d, k3d, a0, 0u, a2, 0u,
                             __float_as_uint(b.x), __float_as_uint(b.y));
                }
                int g = lr;
#pragma unroll
                for (int cc = 0; cc < 2; cc++) {
                    int j = q * 8 + 2 * lc + cc;
                    if (j < 164) {
                        float acc = (cc ? k1v : k0v) + bp[j];
                        int r = j / 41, w = j - r * 41;
                        if (w < D_) S[OFF_SKT + g * 160 + r * 40 + w] = tanh_acc(acc);
                        else        S[OFF_SSIG + g * 4 + r] = sigm(acc);
                    }
                }
            }
        }
#pragma unroll
        for (int s = 0; s < 2; s++) {
            int p = tid + s * TPB;
            int g = p >> 7, n = p & 127;
            const float* Mr = S + OFF_SM + g * NSLOT * MSTR + n * MSTR;
            float ss = 0.f;
            for (int d = 0; d < D_; d++) ss = fmaf(Mr[d], Mr[d], ss);
            S[OFF_MN + p] = __fdiv_rn(1.f, __fsqrt_rn(ss) + 1e-8f);   // store rinv (same math, relocated)
        }
        __syncthreads();

        // ---- D: key norms (tid<32) + LU selection (warps 8..15) ----
        if (tid < 32) {
            int g = tid >> 2, r = tid & 3;
            const float* kk = S + OFF_SKT + g * 160 + r * 40;
            float ss = 0.f;
            for (int d = 0; d < D_; d++) ss = fmaf(kk[d], kk[d], ss);
            S[OFF_KN + tid] = __fsqrt_rn(ss) + 1e-8f;
        } else if (warp >= 8 && warp < 16) {
            int g = warp - 8;
            const float* wu = S + OFF_WU + g * NSLOT;
            float v0 = wu[lane], v1 = wu[lane + 32], v2 = wu[lane + 64], v3 = wu[lane + 96];
            int i0 = lane, i1 = lane + 32, i2 = lane + 64, i3 = lane + 96;
#pragma unroll
            for (int s = 0; s < R_; s++) {
                float bv = v0; int bi = i0;
                if (v1 < bv || (v1 == bv && i1 < bi)) { bv = v1; bi = i1; }
                if (v2 < bv || (v2 == bv && i2 < bi)) { bv = v2; bi = i2; }
                if (v3 < bv || (v3 == bv && i3 < bi)) { bv = v3; bi = i3; }
#pragma unroll
                for (int o = 16; o > 0; o >>= 1) {
                    float ov = __shfl_xor_sync(0xffffffffu, bv, o);
                    int   oi = __shfl_xor_sync(0xffffffffu, bi, o);
                    if (ov < bv || (ov == bv && oi < bi)) { bv = ov; bi = oi; }
                }
                if (lane == 0) s_luI[g * 4 + s] = bi;
                if      (bi == i0) v0 = 3.0e38f;
                else if (bi == i1) v1 = 3.0e38f;
                else if (bi == i2) v2 = 3.0e38f;
                else if (bi == i3) v3 = 3.0e38f;
            }
        }
        __syncthreads();

        // ---- E: round keys; build skn ----
#pragma unroll
        for (int s = 0; s < 3; s++) {
            int i = tid + s * TPB;
            if (i < GB * 160) {
                int g = i / 160, j = i - g * 160;
                int r = j / 40;
                float raw = S[OFF_SKT + i];
                float nrm = S[OFF_KN + g * 4 + r];
                S[OFF_SKN + i] = tf32r(__fdiv_rn(raw, nrm));
                S[OFF_SKT + i] = tf32r(raw);
            }
        }
        __syncthreads();

        // ---- F: cosine logits via mma — warp g computes w_r[g] = Mn[g] @ skn[g]^T ----
        if (warp < GB) {
            int g = warp;
            const float* Mg = S + OFF_SM + g * NSLOT * MSTR;
            const float* ri = S + OFF_MN + g * NSLOT;          // rinv per row
            const float* kn = S + OFF_SKN + g * 160;
            float cF[8][4];
#pragma unroll
            for (int mt = 0; mt < 8; mt++) {
                cF[mt][0] = 0.f; cF[mt][1] = 0.f; cF[mt][2] = 0.f; cF[mt][3] = 0.f;
            }
#pragma unroll
            for (int mt = 0; mt < 8; mt++) {
                int r0 = mt * 16 + lr, r1 = r0 + 8;
                float ri0 = ri[r0], ri1 = ri[r1];
                const float* M0 = Mg + r0 * MSTR;
                const float* M1 = Mg + r1 * MSTR;
#pragma unroll
                for (int k8 = 0; k8 < 5; k8++) {
                    int kk = k8 * 8;
                    uint32_t b0 = 0u, b1 = 0u;
                    if (lr < 4) {
                        b0 = __float_as_uint(kn[lr * 40 + kk + lc]);
                        b1 = __float_as_uint(kn[lr * 40 + kk + lc + 4]);
                    }
                    uint32_t a0 = __float_as_uint(tf32r(M0[kk + lc] * ri0));
                    uint32_t a1 = __float_as_uint(tf32r(M1[kk + lc] * ri1));
                    uint32_t a2 = __float_as_uint(tf32r(M0[kk + lc + 4] * ri0));
                    uint32_t a3 = __float_as_uint(tf32r(M1[kk + lc + 4] * ri1));
                    mma_tf32(cF[mt][0], cF[mt][1], cF[mt][2], cF[mt][3],
                             a0, a1, a2, a3, b0, b1);
                }
            }
            float* sw = S + OFF_SWR + g * 512;
            if (lc < 2) {   // output cols 2lc, 2lc+1 in [0,4)
#pragma unroll
                for (int mt = 0; mt < 8; mt++) {
                    int row0 = mt * 16 + lr;
                    sw[(2 * lc)     * 128 + row0]     = cF[mt][0];
                    sw[(2 * lc + 1) * 128 + row0]     = cF[mt][1];
                    sw[(2 * lc)     * 128 + row0 + 8] = cF[mt][2];
                    sw[(2 * lc + 1) * 128 + row0 + 8] = cF[mt][3];
                }
            }
        }
        __syncthreads();

        // ---- G: softmax per (g,r) ----
        for (int row = warp; row < GB * R_; row += NW) {
            int g = row >> 2, r = row & 3;
            float* sw = S + OFF_SWR + g * 512 + r * 128;
            float v0 = sw[lane], v1 = sw[lane + 32], v2 = sw[lane + 64], v3 = sw[lane + 96];
            float mx = fmaxf(fmaxf(v0, v1), fmaxf(v2, v3));
            for (int o = 16; o > 0; o >>= 1) mx = fmaxf(mx, __shfl_xor_sync(0xffffffffu, mx, o));
            float e0 = exp_acc(v0 - mx), e1 = exp_acc(v1 - mx), e2 = exp_acc(v2 - mx), e3 = exp_acc(v3 - mx);
            float ssum = e0 + e1 + e2 + e3;
            for (int o = 16; o > 0; o >>= 1) ssum += __shfl_xor_sync(0xffffffffu, ssum, o);
            sw[lane]      = __fdiv_rn(e0, ssum);
            sw[lane + 32] = __fdiv_rn(e1, ssum);
            sw[lane + 64] = __fdiv_rn(e2, ssum);
            sw[lane + 96] = __fdiv_rn(e3, ssum);
        }
        __syncthreads();

        // ---- H: usage update + wrOld<-swr + memory write + round swr in place ----
#pragma unroll
        for (int s = 0; s < 2; s++) {
            int p = tid + s * TPB;
            int g = p >> 7, n = p & 127;
            float* wro = S + OFF_WRO + g * 512;
            float* sw  = S + OFF_SWR + g * 512;
            int lu0 = s_luI[g*4], lu1 = s_luI[g*4+1], lu2 = s_luI[g*4+2], lu3 = s_luI[g*4+3];
            float wlu = (n == lu0 || n == lu1 || n == lu2 || n == lu3) ? 1.f : 0.f;
            float sg0 = S[OFF_SSIG + g*4], sg1 = S[OFF_SSIG + g*4+1];
            float sg2 = S[OFF_SSIG + g*4+2], sg3 = S[OFF_SSIG + g*4+3];
            float wo0 = wro[n], wo1 = wro[128+n], wo2 = wro[256+n], wo3 = wro[384+n];
            float ww0 = sg0 * wo0 + (1.f - sg0) * wlu;
            float ww1 = sg1 * wo1 + (1.f - sg1) * wlu;
            float ww2 = sg2 * wo2 + (1.f - sg2) * wlu;
            float ww3 = sg3 * wo3 + (1.f - sg3) * wlu;
            float sr0 = sw[n], sr1 = sw[128+n], sr2 = sw[256+n], sr3 = sw[384+n];
            float v = 0.95f * S[OFF_WU + p];
            v += sr0 + ww0; v += sr1 + ww1; v += sr2 + ww2; v += sr3 + ww3;
            S[OFF_WU + p] = v;
            wro[n] = sr0; wro[128+n] = sr1; wro[256+n] = sr2; wro[384+n] = sr3;
            sw[n] = tf32r(sr0); sw[128+n] = tf32r(sr1); sw[256+n] = tf32r(sr2); sw[384+n] = tf32r(sr3);
            float wt0 = tf32r(ww0), wt1 = tf32r(ww1), wt2 = tf32r(ww2), wt3 = tf32r(ww3);
            float* Mr = S + OFF_SM + g * NSLOT * MSTR + n * MSTR;
            const float* kT = S + OFF_SKT + g * 160;
            bool zero_base = (n == lu3);
            for (int d = 0; d < D_; d++) {
                float base = zero_base ? 0.f : Mr[d];
                float add = 0.f;
                add = fmaf(wt0, kT[d],       add);
                add = fmaf(wt1, kT[40 + d],  add);
                add = fmaf(wt2, kT[80 + d],  add);
                add = fmaf(wt3, kT[120 + d], add);
                Mr[d] = base + add;
            }
        }
        __syncthreads();

        // ---- J: read einsum via mma — warp g (<8) computes r_new[g] = swr[g] @ M[g] ----
        if (warp < GB) {
            int g = warp;
            const float* swB = S + OFF_SWR + g * 512;
            const float* Mg  = S + OFF_SM + g * NSLOT * MSTR;
            float cJ[5][4];
#pragma unroll
            for (int nt = 0; nt < 5; nt++) {
                cJ[nt][0] = 0.f; cJ[nt][1] = 0.f; cJ[nt][2] = 0.f; cJ[nt][3] = 0.f;
            }
#pragma unroll
            for (int k8 = 0; k8 < 16; k8++) {
                int kk = k8 * 8;
                uint32_t a0 = 0u, a2 = 0u;
                if (lr < 4) {
                    a0 = __float_as_uint(swB[lr * 128 + kk + lc]);
                    a2 = __float_as_uint(swB[lr * 128 + kk + lc + 4]);
                }
#pragma unroll
                for (int nt = 0; nt < 5; nt++) {
                    int d0 = nt * 8 + lr;
                    uint32_t b0 = __float_as_uint(tf32r(Mg[(kk + lc) * MSTR + d0]));
                    uint32_t b1 = __float_as_uint(tf32r(Mg[(kk + lc + 4) * MSTR + d0]));
                    mma_tf32(cJ[nt][0], cJ[nt][1], cJ[nt][2], cJ[nt][3],
                             a0, 0u, a2, 0u, b0, b1);
                }
            }
            if (lr < 4) {
#pragma unroll
                for (int nt = 0; nt < 5; nt++) {
                    int d = nt * 8 + 2 * lc;
                    S[OFF_RHT + g * 361 + lr * 40 + d]     = tf32r(cJ[nt][0]);
                    S[OFF_RHT + g * 361 + lr * 40 + d + 1] = tf32r(cJ[nt][1]);
                }
            }
        }
        __syncthreads();

        // ---- K: classifier (transposed Wc, coalesced) ----
        for (int o = warp; o < GB * C_; o += NW) {
            int g = o / C_, cl = o - g * C_;
            const float* rh = S + OFF_RHT + g * 361;
            const float* wc = g_WcT + cl * KRH;
            float acc = 0.f;
            for (int j = lane; j < KRH; j += 32) {
                float v = (j < H_) ? rh[R_*D_ + j] : rh[j - H_];
                acc = fmaf(v, wc[j], acc);
            }
#pragma unroll
            for (int o2 = 16; o2 > 0; o2 >>= 1) acc += __shfl_xor_sync(0xffffffffu, acc, o2);
            if (lane == 0) S[OFF_SLOG + o] = acc + bc[cl];
        }
        __syncthreads();

        // ---- L: probs + loss/acc rows ----
        if (tid < GB) {
            int g = tid;
            int m = (bb + g) * T_ + t;
            const float* lg = S + OFF_SLOG + g * C_;
            float mx = lg[0]; int am = 0;
            for (int c = 1; c < C_; c++) if (lg[c] > mx) { mx = lg[c]; am = c; }
            float e[C_], ssum = 0.f;
            for (int c = 0; c < C_; c++) { e[c] = exp_acc(lg[c] - mx); ssum += e[c]; }
            float pr[C_];
            for (int c = 0; c < C_; c++) { pr[c] = __fdiv_rn(e[c], ssum); out[m * C_ + c] = pr[c]; }
            float mp = pr[0];
            for (int c = 1; c < C_; c++) mp = fmaxf(mp, pr[c]);
            float se = 0.f;
            for (int c = 0; c < C_; c++) se += exp_acc(pr[c] - mp);
            int lab = labels[m];
            g_rowloss[m] = (float)(log((double)se)) + mp - pr[lab];
            g_rowcorr[m] = (am == lab) ? 1.f : 0.f;
        }
        __syncthreads();
    }
}

// ---------------- deterministic final reduction ----------------
__global__ __launch_bounds__(1024) void finalize_kernel(float* __restrict__ out) {
    __shared__ float sl[1024], sa[1024];
    int tid = threadIdx.x;
    float l = 0.f, a = 0.f;
    for (int i = tid; i < BT; i += 1024) { l += g_rowloss[i]; a += g_rowcorr[i]; }
    sl[tid] = l; sa[tid] = a;
    __syncthreads();
    for (int s = 512; s > 0; s >>= 1) {
        if (tid < s) { sl[tid] += sl[tid + s]; sa[tid] += sa[tid + s]; }
        __syncthreads();
    }
    if (tid == 0) {
        out[BT * C_]     = __fdiv_rn(sl[0], (float)BT);
        out[BT * C_ + 1] = __fdiv_rn(sa[0], (float)BT);
    }
}

// ---------------- launch ----------------
extern "C" void kernel_launch(void* const* d_in, const int* in_sizes, int n_in,
                              void* d_out, int out_size) {
    const float* images = (const float*)d_in[0];
    const int*   labels = (const int*)d_in[1];
    const float* Wx     = (const float*)d_in[2];
    const float* Wh     = (const float*)d_in[3];
    const float* b_lstm = (const float*)d_in[4];
    const float* Wp     = (const float*)d_in[5];
    const float* bp     = (const float*)d_in[6];
    const float* Wc     = (const float*)d_in[7];
    const float* bc     = (const float*)d_in[8];
    float* out = (float*)d_out;

    float* pXpre;
    cudaGetSymbolAddress((void**)&pXpre, g_Xpre);

    cudaFuncSetAttribute(fused_kernel, cudaFuncAttributeMaxDynamicSharedMemorySize, SMEM_BYTES);
    cudaFuncSetAttribute(gemm0_kernel, cudaFuncAttributeMaxDynamicSharedMemorySize, G0_SMEM_FLOATS * 4);

    init_kernel<<<320, 256>>>(Wx, Wh, Wp, Wc);

    {
        dim3 grid(7, BT / 128);
        gemm0_kernel<<<grid, 256, G0_SMEM_FLOATS * 4>>>(images, Wx, b_lstm, labels, pXpre);
    }

    fused_kernel<<<NBLK, TPB, SMEM_BYTES>>>(bp, bc, labels, out);

    finalize_kernel<<<1, 1024>>>(out);
}